// round 8
// baseline (speedup 1.0000x reference)
#include <cuda_runtime.h>
#include <math.h>
#include <stdint.h>

#define TOK   2048
#define BATCH 8
#define NEMBD 768
#define HS    64
#define MROWS (BATCH*TOK)          // 16384

// ---------------- scratch (device globals; no allocation allowed) ----------
// q/k/v hold tf32-converted bits (q pre-scaled by 1/8)
static __device__ uint32_t g_q[MROWS*HS];
static __device__ uint32_t g_k[MROWS*HS];
static __device__ uint32_t g_v[MROWS*HS];
// pre-converted weights (tf32 bits): [Wq | Wk | Wv]
static __device__ uint32_t g_wt[3*NEMBD*HS];

// split-K partials: unit = ((b*32 + qb)*4 + chunk), 1024 units x 64 rows
static __device__ float g_part_o[1024*64*HS];
static __device__ float g_part_m[1024*64];
static __device__ float g_part_l[1024*64];

// ---------------- helpers ---------------------------------------------------
__device__ __forceinline__ uint32_t f2tf32(float f) {
    uint32_t u;
    asm("cvt.rna.tf32.f32 %0, %1;" : "=r"(u) : "f"(f));
    return u;
}
__device__ __forceinline__ uint32_t u2tf32(uint32_t bits) {
    return f2tf32(__uint_as_float(bits));
}

__device__ __forceinline__ void mma_tf32(float c[4],
                                         uint32_t a0, uint32_t a1, uint32_t a2, uint32_t a3,
                                         uint32_t b0, uint32_t b1) {
    asm volatile(
        "mma.sync.aligned.m16n8k8.row.col.f32.tf32.tf32.f32 "
        "{%0,%1,%2,%3},{%4,%5,%6,%7},{%8,%9},{%0,%1,%2,%3};"
        : "+f"(c[0]), "+f"(c[1]), "+f"(c[2]), "+f"(c[3])
        : "r"(a0), "r"(a1), "r"(a2), "r"(a3), "r"(b0), "r"(b1));
}

__device__ __forceinline__ void cp_async16(uint32_t dst_smem, const void* src) {
    asm volatile("cp.async.cg.shared.global [%0], [%1], 16;"
                 :: "r"(dst_smem), "l"(src));
}
__device__ __forceinline__ uint32_t smem_u32(const void* p) {
    return (uint32_t)__cvta_generic_to_shared(p);
}

// ---------------- weight pre-conversion: fp32 -> tf32 bits ------------------
__global__ __launch_bounds__(256) void w_convert(const float* __restrict__ Wq,
                                                 const float* __restrict__ Wk,
                                                 const float* __restrict__ Wv) {
    const int i4 = blockIdx.x * 256 + threadIdx.x;     // uint4 index, 0..36863
    const int per = NEMBD * HS / 4;                    // 12288 float4 per matrix
    const float* src = (i4 < per) ? Wq : (i4 < 2 * per) ? Wk : Wv;
    const int off = (i4 % per) * 4;
    float4 w = *(const float4*)&src[off];
    *(uint4*)&g_wt[(i4 / per) * NEMBD * HS + off] =
        make_uint4(f2tf32(w.x), f2tf32(w.y), f2tf32(w.z), f2tf32(w.w));
}

// ---------------- QKV projection: out[M,64] = x[M,768] @ W[768,64] ---------
// block = 256 threads (8 warps), tile 128 rows x 64 cols, BK = 16, 3-stage cp.async
// warp w owns rows w*16 .. w*16+15
// ASTQ=20 (=20 mod 32): A-frag banks distinct across warp -> conflict-free
// BSTQ=72 (=8 mod 32):  B-frag bank = 8tig+g+const        -> conflict-free
#define ASTQ 20
#define BSTQ 72
#define KT   48    // 768/16 BK-iterations
__global__ __launch_bounds__(256) void qkv_gemm_tc(const float* __restrict__ x) {
    __shared__ uint32_t As[3][128 * ASTQ];   // raw fp32 bits
    __shared__ uint32_t Bs[3][16 * BSTQ];    // tf32 bits (pre-converted)

    const uint32_t* W = g_wt + blockIdx.y * (NEMBD * HS);
    uint32_t* out;
    float oscale;
    if (blockIdx.y == 0)      { out = g_q; oscale = 0.125f; }
    else if (blockIdx.y == 1) { out = g_k; oscale = 1.0f; }
    else                      { out = g_v; oscale = 1.0f; }

    const int tid  = threadIdx.x;
    const int warp = tid >> 5;
    const int lane = tid & 31;
    const int g    = lane >> 2;
    const int tig  = lane & 3;
    const int row0 = blockIdx.x * 128;

    // cp.async mapping
    // A: 512 uint4 slots, thread does slots tid, tid+256: r = idx>>2, c4 = (idx&3)*4
    // B: 256 uint4 slots, thread does slot tid:           r = tid>>4, c4 = (tid&15)*4
    const int ar0 = tid >> 2;
    const int ac  = (tid & 3) * 4;
    const int br  = tid >> 4;
    const int bc  = (tid & 15) * 4;

    float acc[8][4];
#pragma unroll
    for (int nt = 0; nt < 8; nt++)
#pragma unroll
        for (int i = 0; i < 4; i++) acc[nt][i] = 0.f;

#define QKV_ISSUE(s, k0)                                                          \
    do {                                                                          \
        _Pragma("unroll")                                                         \
        for (int i = 0; i < 2; i++) {                                             \
            int r = ar0 + i * 64;                                                 \
            cp_async16(smem_u32(&As[s][r * ASTQ + ac]),                           \
                       &x[(size_t)(row0 + r) * NEMBD + (k0) + ac]);               \
        }                                                                         \
        cp_async16(smem_u32(&Bs[s][br * BSTQ + bc]),                              \
                   &W[(size_t)((k0) + br) * HS + bc]);                            \
        asm volatile("cp.async.commit_group;");                                   \
    } while (0)

    QKV_ISSUE(0, 0);
    QKV_ISSUE(1, 16);

    for (int it = 0; it < KT; it++) {
        if (it == KT - 1) asm volatile("cp.async.wait_group 0;");
        else              asm volatile("cp.async.wait_group 1;");
        __syncthreads();

        if (it + 2 < KT) QKV_ISSUE((it + 2) % 3, (it + 2) * 16);

        const uint32_t* as = As[it % 3];
        const uint32_t* bs = Bs[it % 3];
        const int m0 = warp * 16;

#pragma unroll
        for (int kk = 0; kk < 2; kk++) {
            uint32_t a0 = u2tf32(as[(m0 + g) * ASTQ + kk * 8 + tig]);
            uint32_t a1 = u2tf32(as[(m0 + g + 8) * ASTQ + kk * 8 + tig]);
            uint32_t a2 = u2tf32(as[(m0 + g) * ASTQ + kk * 8 + tig + 4]);
            uint32_t a3 = u2tf32(as[(m0 + g + 8) * ASTQ + kk * 8 + tig + 4]);
#pragma unroll
            for (int nt = 0; nt < 8; nt++) {
                uint32_t b0 = bs[(kk * 8 + tig) * BSTQ + nt * 8 + g];
                uint32_t b1 = bs[(kk * 8 + tig + 4) * BSTQ + nt * 8 + g];
                mma_tf32(acc[nt], a0, a1, a2, a3, b0, b1);
            }
        }
    }

    // epilogue: scale (Q only) + convert to tf32 bits
    const int r0 = row0 + warp * 16 + g;
#pragma unroll
    for (int nt = 0; nt < 8; nt++) {
        const int c = nt * 8 + 2 * tig;
        *(uint2*)&out[(size_t)r0 * HS + c] =
            make_uint2(f2tf32(acc[nt][0] * oscale), f2tf32(acc[nt][1] * oscale));
        *(uint2*)&out[(size_t)(r0 + 8) * HS + c] =
            make_uint2(f2tf32(acc[nt][2] * oscale), f2tf32(acc[nt][3] * oscale));
    }
}

// ---------------- flash attention partial (tensor cores, split along keys) --
// grid = (4 chunks, 32 qblocks, 8 batches), 128 threads (4 warps)
// block handles 64 q rows; warp w handles rows w*16 .. w*16+15
// Ksh stride 68 (=4 mod 32): K-frag rows indexed by nt*8+g -> bank 4g+tig, conflict-free
// Vsh stride 72 (=8 mod 32): V-frag rows indexed by ks*8+tig -> bank 8tig+g, conflict-free
#define KSTK 68
#define KSTV 72
__global__ __launch_bounds__(128) void attn_partial_tc() {
    __shared__ uint32_t Ksh[64 * KSTK];
    __shared__ uint32_t Vsh[64 * KSTV];

    const int chunk = blockIdx.x;
    const int qb    = blockIdx.y;        // 0..31, 64 rows each
    const int b     = blockIdx.z;

    const int nkb = qb + 1;              // 64-key tiles needed (causal)
    const int kb0 = chunk * 8;
    if (kb0 >= nkb) return;
    const int kb1 = (kb0 + 8 < nkb) ? kb0 + 8 : nkb;

    const int tid  = threadIdx.x;
    const int warp = tid >> 5;
    const int lane = tid & 31;
    const int g    = lane >> 2;
    const int tig  = lane & 3;
    const int qrow0 = qb * 64;           // block's first q row (within batch)

    // ---- stage Q (already tf32+scaled) through Vsh, pull fragments ---------
#pragma unroll
    for (int i = 0; i < 8; i++) {
        int idx = tid + i * 128;
        int r   = idx >> 4;
        int c4  = (idx & 15) * 4;
        *(uint4*)&Vsh[r * KSTV + c4] =
            *(const uint4*)&g_q[((size_t)(b * TOK + qrow0 + r)) * HS + c4];
    }
    __syncthreads();

    uint32_t qf[8][4];
    const int mrow = warp * 16;          // warp's first local row
#pragma unroll
    for (int ks = 0; ks < 8; ks++) {
        qf[ks][0] = Vsh[(mrow + g) * KSTV + ks * 8 + tig];
        qf[ks][1] = Vsh[(mrow + g + 8) * KSTV + ks * 8 + tig];
        qf[ks][2] = Vsh[(mrow + g) * KSTV + ks * 8 + tig + 4];
        qf[ks][3] = Vsh[(mrow + g + 8) * KSTV + ks * 8 + tig + 4];
    }
    __syncthreads();

    float oacc[8][4];
#pragma unroll
    for (int nt = 0; nt < 8; nt++)
#pragma unroll
        for (int i = 0; i < 4; i++) oacc[nt][i] = 0.f;

    float m0r = -INFINITY, m1r = -INFINITY;   // rows g and g+8
    float l0 = 0.f, l1 = 0.f;

    const int rg0 = qrow0 + mrow + g;         // global (in-batch) q rows
    const int rg1 = rg0 + 8;

    // shuffle sources for C-frag -> A-frag redistribution
    const int src0 = (lane & ~3) | (tig >> 1);
    const int src1 = src0 + 2;
    const bool odd = (tig & 1);

    for (int kb = kb0; kb < kb1; kb++) {
        // ---- load K and V tiles (pure uint4 copies, already tf32) ---------
#pragma unroll
        for (int i = 0; i < 8; i++) {
            int idx = tid + i * 128;
            int r   = idx >> 4;
            int c4  = (idx & 15) * 4;
            size_t base = ((size_t)(b * TOK + kb * 64 + r)) * HS + c4;
            *(uint4*)&Ksh[r * KSTK + c4] = *(const uint4*)&g_k[base];
            *(uint4*)&Vsh[r * KSTV + c4] = *(const uint4*)&g_v[base];
        }
        __syncthreads();

        // ---- S = Q K^T (16 x 64 per warp) ---------------------------------
        float sacc[8][4];
#pragma unroll
        for (int nt = 0; nt < 8; nt++) {
#pragma unroll
            for (int i = 0; i < 4; i++) sacc[nt][i] = 0.f;
#pragma unroll
            for (int ks = 0; ks < 8; ks++) {
                uint32_t b0 = Ksh[(nt * 8 + g) * KSTK + ks * 8 + tig];
                uint32_t b1 = Ksh[(nt * 8 + g) * KSTK + ks * 8 + tig + 4];
                mma_tf32(sacc[nt], qf[ks][0], qf[ks][1], qf[ks][2], qf[ks][3], b0, b1);
            }
        }

        // ---- causal mask (only the diagonal tile can clip) ----------------
        if (kb == qb) {
            const int colbase = kb * 64;
#pragma unroll
            for (int nt = 0; nt < 8; nt++) {
                const int c0 = colbase + nt * 8 + 2 * tig;
                if (c0 > rg0)     sacc[nt][0] = -INFINITY;
                if (c0 + 1 > rg0) sacc[nt][1] = -INFINITY;
                if (c0 > rg1)     sacc[nt][2] = -INFINITY;
                if (c0 + 1 > rg1) sacc[nt][3] = -INFINITY;
            }
        }

        // ---- online softmax -----------------------------------------------
        float mx0 = -INFINITY, mx1 = -INFINITY;
#pragma unroll
        for (int nt = 0; nt < 8; nt++) {
            mx0 = fmaxf(mx0, fmaxf(sacc[nt][0], sacc[nt][1]));
            mx1 = fmaxf(mx1, fmaxf(sacc[nt][2], sacc[nt][3]));
        }
        mx0 = fmaxf(mx0, __shfl_xor_sync(0xffffffffu, mx0, 1));
        mx0 = fmaxf(mx0, __shfl_xor_sync(0xffffffffu, mx0, 2));
        mx1 = fmaxf(mx1, __shfl_xor_sync(0xffffffffu, mx1, 1));
        mx1 = fmaxf(mx1, __shfl_xor_sync(0xffffffffu, mx1, 2));

        const float mn0 = fmaxf(m0r, mx0);
        const float mn1 = fmaxf(m1r, mx1);
        const float alpha0 = __expf(m0r - mn0);   // first iter: exp(-inf)=0
        const float alpha1 = __expf(m1r - mn1);
        m0r = mn0; m1r = mn1;

        float ps0 = 0.f, ps1 = 0.f;
#pragma unroll
        for (int nt = 0; nt < 8; nt++) {
            sacc[nt][0] = __expf(sacc[nt][0] - mn0);
            sacc[nt][1] = __expf(sacc[nt][1] - mn0);
            sacc[nt][2] = __expf(sacc[nt][2] - mn1);
            sacc[nt][3] = __expf(sacc[nt][3] - mn1);
            ps0 += sacc[nt][0] + sacc[nt][1];
            ps1 += sacc[nt][2] + sacc[nt][3];
        }
        ps0 += __shfl_xor_sync(0xffffffffu, ps0, 1);
        ps0 += __shfl_xor_sync(0xffffffffu, ps0, 2);
        ps1 += __shfl_xor_sync(0xffffffffu, ps1, 1);
        ps1 += __shfl_xor_sync(0xffffffffu, ps1, 2);
        l0 = l0 * alpha0 + ps0;
        l1 = l1 * alpha1 + ps1;

#pragma unroll
        for (int nt = 0; nt < 8; nt++) {
            oacc[nt][0] *= alpha0; oacc[nt][1] *= alpha0;
            oacc[nt][2] *= alpha1; oacc[nt][3] *= alpha1;
        }

        // ---- O += P V : P redistributed C-frag -> A-frag via shuffles ------
#pragma unroll
        for (int ks = 0; ks < 8; ks++) {
            const float p0a = __shfl_sync(0xffffffffu, sacc[ks][0], src0);
            const float p1a = __shfl_sync(0xffffffffu, sacc[ks][1], src0);
            const float p2a = __shfl_sync(0xffffffffu, sacc[ks][2], src0);
            const float p3a = __shfl_sync(0xffffffffu, sacc[ks][3], src0);
            const float p0b = __shfl_sync(0xffffffffu, sacc[ks][0], src1);
            const float p1b = __shfl_sync(0xffffffffu, sacc[ks][1], src1);
            const float p2b = __shfl_sync(0xffffffffu, sacc[ks][2], src1);
            const float p3b = __shfl_sync(0xffffffffu, sacc[ks][3], src1);
            const uint32_t pa0 = f2tf32(odd ? p1a : p0a);
            const uint32_t pa1 = f2tf32(odd ? p3a : p2a);
            const uint32_t pa2 = f2tf32(odd ? p1b : p0b);
            const uint32_t pa3 = f2tf32(odd ? p3b : p2b);
#pragma unroll
            for (int nt = 0; nt < 8; nt++) {
                uint32_t b0 = Vsh[(ks * 8 + tig) * KSTV + nt * 8 + g];
                uint32_t b1 = Vsh[(ks * 8 + tig + 4) * KSTV + nt * 8 + g];
                mma_tf32(oacc[nt], pa0, pa1, pa2, pa3, b0, b1);
            }
        }
        __syncthreads();   // before next tile overwrites Ksh/Vsh
    }

    // ---- write partials ----------------------------------------------------
    const int unit = (b * 32 + qb) * 4 + chunk;
    const int lr0 = mrow + g;            // local rows within 64
    const int lr1 = lr0 + 8;
    if (tig == 0) {
        g_part_m[unit * 64 + lr0] = m0r;
        g_part_m[unit * 64 + lr1] = m1r;
        g_part_l[unit * 64 + lr0] = l0;
        g_part_l[unit * 64 + lr1] = l1;
    }
#pragma unroll
    for (int nt = 0; nt < 8; nt++) {
        const int c = nt * 8 + 2 * tig;
        *(float2*)&g_part_o[((size_t)(unit * 64 + lr0)) * HS + c] =
            make_float2(oacc[nt][0], oacc[nt][1]);
        *(float2*)&g_part_o[((size_t)(unit * 64 + lr1)) * HS + c] =
            make_float2(oacc[nt][2], oacc[nt][3]);
    }
}

// ---------------- combine split-K partials ---------------------------------
__global__ __launch_bounds__(128) void attn_combine(float* __restrict__ out) {
    const int row = blockIdx.x * 128 + threadIdx.x;   // 0..16383 (b*2048+t)
    const int b = row >> 11;
    const int t = row & 2047;
    const int qb = t >> 6;
    const int lane = t & 63;
    const int nchunk = (qb + 1 + 7) / 8;              // 1..4 active chunks
    const int base_unit = (b * 32 + qb) * 4;

    float M = -INFINITY;
    for (int c = 0; c < nchunk; c++)
        M = fmaxf(M, g_part_m[(base_unit + c) * 64 + lane]);

    float w[4];
    float L = 0.f;
    for (int c = 0; c < nchunk; c++) {
        float wm = __expf(g_part_m[(base_unit + c) * 64 + lane] - M);
        w[c] = wm;
        L += wm * g_part_l[(base_unit + c) * 64 + lane];
    }
    const float inv = 1.f / L;

    float* op = out + (size_t)row * HS;
#pragma unroll
    for (int i = 0; i < 16; i++) {
        float4 acc = make_float4(0.f, 0.f, 0.f, 0.f);
        for (int c = 0; c < nchunk; c++) {
            const float* po = g_part_o + ((size_t)((base_unit + c) * 64 + lane)) * HS;
            float4 v = *(const float4*)&po[i * 4];
            acc.x += w[c] * v.x; acc.y += w[c] * v.y;
            acc.z += w[c] * v.z; acc.w += w[c] * v.w;
        }
        acc.x *= inv; acc.y *= inv; acc.z *= inv; acc.w *= inv;
        *(float4*)&op[i * 4] = acc;
    }
}

// ---------------- launch ----------------------------------------------------
extern "C" void kernel_launch(void* const* d_in, const int* in_sizes, int n_in,
                              void* d_out, int out_size) {
    const float* x  = (const float*)d_in[0];
    const float* Wk = (const float*)d_in[1];
    const float* Wq = (const float*)d_in[2];
    const float* Wv = (const float*)d_in[3];
    float* out = (float*)d_out;

    w_convert<<<dim3(3 * NEMBD * HS / 4 / 256), 256>>>(Wq, Wk, Wv);
    qkv_gemm_tc<<<dim3(MROWS / 128, 3), 256>>>(x);
    attn_partial_tc<<<dim3(4, 32, BATCH), 128>>>();
    attn_combine<<<dim3(MROWS / 128), 128>>>(out);
}

// round 10
// speedup vs baseline: 1.0952x; 1.0952x over previous
#include <cuda_runtime.h>
#include <math.h>
#include <stdint.h>

#define TOK   2048
#define BATCH 8
#define NEMBD 768
#define HS    64
#define MROWS (BATCH*TOK)          // 16384

// ---------------- scratch (device globals; no allocation allowed) ----------
// q/k/v hold tf32-converted bits (q pre-scaled by 1/8)
static __device__ uint32_t g_q[MROWS*HS];
static __device__ uint32_t g_k[MROWS*HS];
static __device__ uint32_t g_v[MROWS*HS];

// split-K partials: unit = ((b*32 + qb)*4 + chunk), 1024 units x 64 rows
static __device__ float g_part_o[1024*64*HS];
static __device__ float g_part_m[1024*64];
static __device__ float g_part_l[1024*64];

// ---------------- helpers ---------------------------------------------------
__device__ __forceinline__ uint32_t f2tf32(float f) {
    uint32_t u;
    asm("cvt.rna.tf32.f32 %0, %1;" : "=r"(u) : "f"(f));
    return u;
}
__device__ __forceinline__ uint32_t u2tf32(uint32_t bits) {
    return f2tf32(__uint_as_float(bits));
}

__device__ __forceinline__ void mma_tf32(float c[4],
                                         uint32_t a0, uint32_t a1, uint32_t a2, uint32_t a3,
                                         uint32_t b0, uint32_t b1) {
    asm volatile(
        "mma.sync.aligned.m16n8k8.row.col.f32.tf32.tf32.f32 "
        "{%0,%1,%2,%3},{%4,%5,%6,%7},{%8,%9},{%0,%1,%2,%3};"
        : "+f"(c[0]), "+f"(c[1]), "+f"(c[2]), "+f"(c[3])
        : "r"(a0), "r"(a1), "r"(a2), "r"(a3), "r"(b0), "r"(b1));
}

__device__ __forceinline__ void cp_async16(uint32_t dst_smem, const void* src) {
    asm volatile("cp.async.cg.shared.global [%0], [%1], 16;"
                 :: "r"(dst_smem), "l"(src));
}
__device__ __forceinline__ uint32_t smem_u32(const void* p) {
    return (uint32_t)__cvta_generic_to_shared(p);
}

// ---------------- QKV projection: out[M,64] = x[M,768] @ W[768,64] ---------
// block = 128 threads (4 warps), tile 128 rows x 64 cols, BK = 16, 3-stage cp.async
// (round-7 proven version: 55.1us)
#define ASTQ 20
#define BSTQ 72
#define KT   48    // 768/16 BK-iterations
__global__ __launch_bounds__(128) void qkv_gemm_tc(const float* __restrict__ x,
                                                   const float* __restrict__ Wk,
                                                   const float* __restrict__ Wq,
                                                   const float* __restrict__ Wv) {
    __shared__ uint32_t As[3][128 * ASTQ];   // raw fp32 bits
    __shared__ uint32_t Bs[3][16 * BSTQ];

    const float* W;
    uint32_t* out;
    float oscale;
    if (blockIdx.y == 0)      { W = Wq; out = g_q; oscale = 0.125f; }
    else if (blockIdx.y == 1) { W = Wk; out = g_k; oscale = 1.0f; }
    else                      { W = Wv; out = g_v; oscale = 1.0f; }

    const int tid  = threadIdx.x;
    const int warp = tid >> 5;
    const int lane = tid & 31;
    const int g    = lane >> 2;
    const int tig  = lane & 3;
    const int row0 = blockIdx.x * 128;

    const int ar = tid >> 2;            // A row for i=0 (rows ar, ar+32, ...)
    const int ac = (tid & 3) * 4;
    const int br = tid >> 4;
    const int bc = (tid & 15) * 4;

    float acc[2][8][4];
#pragma unroll
    for (int mt = 0; mt < 2; mt++)
#pragma unroll
        for (int nt = 0; nt < 8; nt++)
#pragma unroll
            for (int i = 0; i < 4; i++) acc[mt][nt][i] = 0.f;

#define QKV_ISSUE(s, k0)                                                          \
    do {                                                                          \
        _Pragma("unroll")                                                         \
        for (int i = 0; i < 4; i++) {                                             \
            int r = ar + i * 32;                                                  \
            cp_async16(smem_u32(&As[s][r * ASTQ + ac]),                           \
                       &x[(size_t)(row0 + r) * NEMBD + (k0) + ac]);               \
        }                                                                         \
        _Pragma("unroll")                                                         \
        for (int i = 0; i < 2; i++) {                                             \
            int r = br + i * 8;                                                   \
            cp_async16(smem_u32(&Bs[s][r * BSTQ + bc]),                           \
                       &W[(size_t)((k0) + r) * HS + bc]);                         \
        }                                                                         \
        asm volatile("cp.async.commit_group;");                                   \
    } while (0)

    QKV_ISSUE(0, 0);
    QKV_ISSUE(1, 16);

    for (int it = 0; it < KT; it++) {
        if (it == KT - 1) asm volatile("cp.async.wait_group 0;");
        else              asm volatile("cp.async.wait_group 1;");
        __syncthreads();

        if (it + 2 < KT) QKV_ISSUE((it + 2) % 3, (it + 2) * 16);

        const uint32_t* as = As[it % 3];
        const uint32_t* bs = Bs[it % 3];

#pragma unroll
        for (int kk = 0; kk < 2; kk++) {
            uint32_t af[2][4];
#pragma unroll
            for (int mt = 0; mt < 2; mt++) {
                const int m0 = warp * 32 + mt * 16;
                af[mt][0] = u2tf32(as[(m0 + g) * ASTQ + kk * 8 + tig]);
                af[mt][1] = u2tf32(as[(m0 + g + 8) * ASTQ + kk * 8 + tig]);
                af[mt][2] = u2tf32(as[(m0 + g) * ASTQ + kk * 8 + tig + 4]);
                af[mt][3] = u2tf32(as[(m0 + g + 8) * ASTQ + kk * 8 + tig + 4]);
            }
#pragma unroll
            for (int nt = 0; nt < 8; nt++) {
                uint32_t b0 = u2tf32(bs[(kk * 8 + tig) * BSTQ + nt * 8 + g]);
                uint32_t b1 = u2tf32(bs[(kk * 8 + tig + 4) * BSTQ + nt * 8 + g]);
                mma_tf32(acc[0][nt], af[0][0], af[0][1], af[0][2], af[0][3], b0, b1);
                mma_tf32(acc[1][nt], af[1][0], af[1][1], af[1][2], af[1][3], b0, b1);
            }
        }
    }

    // epilogue: scale (Q only) + convert to tf32 bits
#pragma unroll
    for (int mt = 0; mt < 2; mt++) {
        const int r0 = row0 + warp * 32 + mt * 16 + g;
#pragma unroll
        for (int nt = 0; nt < 8; nt++) {
            const int c = nt * 8 + 2 * tig;
            *(uint2*)&out[(size_t)r0 * HS + c] =
                make_uint2(f2tf32(acc[mt][nt][0] * oscale), f2tf32(acc[mt][nt][1] * oscale));
            *(uint2*)&out[(size_t)(r0 + 8) * HS + c] =
                make_uint2(f2tf32(acc[mt][nt][2] * oscale), f2tf32(acc[mt][nt][3] * oscale));
        }
    }
}

// ---------------- flash attention partial (tensor cores, split along keys) --
// grid = (4 chunks, 32 qblocks, 8 batches), 128 threads (4 warps)
#define KSTK 68
#define KSTV 72
__global__ __launch_bounds__(128) void attn_partial_tc() {
    __shared__ uint32_t Ksh[64 * KSTK];
    __shared__ uint32_t Vsh[64 * KSTV];

    const int chunk = blockIdx.x;
    const int qb    = blockIdx.y;        // 0..31, 64 rows each
    const int b     = blockIdx.z;

    const int nkb = qb + 1;              // 64-key tiles needed (causal)
    const int kb0 = chunk * 8;
    if (kb0 >= nkb) return;
    const int kb1 = (kb0 + 8 < nkb) ? kb0 + 8 : nkb;

    const int tid  = threadIdx.x;
    const int warp = tid >> 5;
    const int lane = tid & 31;
    const int g    = lane >> 2;
    const int tig  = lane & 3;
    const int qrow0 = qb * 64;           // block's first q row (within batch)

    // ---- stage Q (already tf32+scaled) through Vsh, pull fragments ---------
#pragma unroll
    for (int i = 0; i < 8; i++) {
        int idx = tid + i * 128;
        int r   = idx >> 4;
        int c4  = (idx & 15) * 4;
        *(uint4*)&Vsh[r * KSTV + c4] =
            *(const uint4*)&g_q[((size_t)(b * TOK + qrow0 + r)) * HS + c4];
    }
    __syncthreads();

    uint32_t qf[8][4];
    const int mrow = warp * 16;          // warp's first local row
#pragma unroll
    for (int ks = 0; ks < 8; ks++) {
        qf[ks][0] = Vsh[(mrow + g) * KSTV + ks * 8 + tig];
        qf[ks][1] = Vsh[(mrow + g + 8) * KSTV + ks * 8 + tig];
        qf[ks][2] = Vsh[(mrow + g) * KSTV + ks * 8 + tig + 4];
        qf[ks][3] = Vsh[(mrow + g + 8) * KSTV + ks * 8 + tig + 4];
    }
    __syncthreads();

    float oacc[8][4];
#pragma unroll
    for (int nt = 0; nt < 8; nt++)
#pragma unroll
        for (int i = 0; i < 4; i++) oacc[nt][i] = 0.f;

    float m0r = -INFINITY, m1r = -INFINITY;   // rows g and g+8
    float l0 = 0.f, l1 = 0.f;

    const int rg0 = qrow0 + mrow + g;         // global (in-batch) q rows
    const int rg1 = rg0 + 8;

    // shuffle sources for C-frag -> A-frag redistribution
    const int src0 = (lane & ~3) | (tig >> 1);
    const int src1 = src0 + 2;
    const bool odd = (tig & 1);

    for (int kb = kb0; kb < kb1; kb++) {
        // ---- load K and V tiles (pure uint4 copies, already tf32) ---------
#pragma unroll
        for (int i = 0; i < 8; i++) {
            int idx = tid + i * 128;
            int r   = idx >> 4;
            int c4  = (idx & 15) * 4;
            size_t base = ((size_t)(b * TOK + kb * 64 + r)) * HS + c4;
            *(uint4*)&Ksh[r * KSTK + c4] = *(const uint4*)&g_k[base];
            *(uint4*)&Vsh[r * KSTV + c4] = *(const uint4*)&g_v[base];
        }
        __syncthreads();

        // ---- S = Q K^T (16 x 64 per warp) ---------------------------------
        float sacc[8][4];
#pragma unroll
        for (int nt = 0; nt < 8; nt++) {
#pragma unroll
            for (int i = 0; i < 4; i++) sacc[nt][i] = 0.f;
#pragma unroll
            for (int ks = 0; ks < 8; ks++) {
                uint32_t b0 = Ksh[(nt * 8 + g) * KSTK + ks * 8 + tig];
                uint32_t b1 = Ksh[(nt * 8 + g) * KSTK + ks * 8 + tig + 4];
                mma_tf32(sacc[nt], qf[ks][0], qf[ks][1], qf[ks][2], qf[ks][3], b0, b1);
            }
        }

        // ---- causal mask (only the diagonal tile can clip) ----------------
        if (kb == qb) {
            const int colbase = kb * 64;
#pragma unroll
            for (int nt = 0; nt < 8; nt++) {
                const int c0 = colbase + nt * 8 + 2 * tig;
                if (c0 > rg0)     sacc[nt][0] = -INFINITY;
                if (c0 + 1 > rg0) sacc[nt][1] = -INFINITY;
                if (c0 > rg1)     sacc[nt][2] = -INFINITY;
                if (c0 + 1 > rg1) sacc[nt][3] = -INFINITY;
            }
        }

        // ---- online softmax -----------------------------------------------
        float mx0 = -INFINITY, mx1 = -INFINITY;
#pragma unroll
        for (int nt = 0; nt < 8; nt++) {
            mx0 = fmaxf(mx0, fmaxf(sacc[nt][0], sacc[nt][1]));
            mx1 = fmaxf(mx1, fmaxf(sacc[nt][2], sacc[nt][3]));
        }
        mx0 = fmaxf(mx0, __shfl_xor_sync(0xffffffffu, mx0, 1));
        mx0 = fmaxf(mx0, __shfl_xor_sync(0xffffffffu, mx0, 2));
        mx1 = fmaxf(mx1, __shfl_xor_sync(0xffffffffu, mx1, 1));
        mx1 = fmaxf(mx1, __shfl_xor_sync(0xffffffffu, mx1, 2));

        const float mn0 = fmaxf(m0r, mx0);
        const float mn1 = fmaxf(m1r, mx1);
        const float alpha0 = __expf(m0r - mn0);   // first iter: exp(-inf)=0
        const float alpha1 = __expf(m1r - mn1);
        m0r = mn0; m1r = mn1;

        float ps0 = 0.f, ps1 = 0.f;
#pragma unroll
        for (int nt = 0; nt < 8; nt++) {
            sacc[nt][0] = __expf(sacc[nt][0] - mn0);
            sacc[nt][1] = __expf(sacc[nt][1] - mn0);
            sacc[nt][2] = __expf(sacc[nt][2] - mn1);
            sacc[nt][3] = __expf(sacc[nt][3] - mn1);
            ps0 += sacc[nt][0] + sacc[nt][1];
            ps1 += sacc[nt][2] + sacc[nt][3];
        }
        ps0 += __shfl_xor_sync(0xffffffffu, ps0, 1);
        ps0 += __shfl_xor_sync(0xffffffffu, ps0, 2);
        ps1 += __shfl_xor_sync(0xffffffffu, ps1, 1);
        ps1 += __shfl_xor_sync(0xffffffffu, ps1, 2);
        l0 = l0 * alpha0 + ps0;
        l1 = l1 * alpha1 + ps1;

#pragma unroll
        for (int nt = 0; nt < 8; nt++) {
            oacc[nt][0] *= alpha0; oacc[nt][1] *= alpha0;
            oacc[nt][2] *= alpha1; oacc[nt][3] *= alpha1;
        }

        // ---- O += P V : P redistributed C-frag -> A-frag via shuffles ------
#pragma unroll
        for (int ks = 0; ks < 8; ks++) {
            const float p0a = __shfl_sync(0xffffffffu, sacc[ks][0], src0);
            const float p1a = __shfl_sync(0xffffffffu, sacc[ks][1], src0);
            const float p2a = __shfl_sync(0xffffffffu, sacc[ks][2], src0);
            const float p3a = __shfl_sync(0xffffffffu, sacc[ks][3], src0);
            const float p0b = __shfl_sync(0xffffffffu, sacc[ks][0], src1);
            const float p1b = __shfl_sync(0xffffffffu, sacc[ks][1], src1);
            const float p2b = __shfl_sync(0xffffffffu, sacc[ks][2], src1);
            const float p3b = __shfl_sync(0xffffffffu, sacc[ks][3], src1);
            const uint32_t pa0 = f2tf32(odd ? p1a : p0a);
            const uint32_t pa1 = f2tf32(odd ? p3a : p2a);
            const uint32_t pa2 = f2tf32(odd ? p1b : p0b);
            const uint32_t pa3 = f2tf32(odd ? p3b : p2b);
#pragma unroll
            for (int nt = 0; nt < 8; nt++) {
                uint32_t b0 = Vsh[(ks * 8 + tig) * KSTV + nt * 8 + g];
                uint32_t b1 = Vsh[(ks * 8 + tig + 4) * KSTV + nt * 8 + g];
                mma_tf32(oacc[nt], pa0, pa1, pa2, pa3, b0, b1);
            }
        }
        __syncthreads();   // before next tile overwrites Ksh/Vsh
    }

    // ---- write partials ----------------------------------------------------
    const int unit = (b * 32 + qb) * 4 + chunk;
    const int lr0 = mrow + g;            // local rows within 64
    const int lr1 = lr0 + 8;
    if (tig == 0) {
        g_part_m[unit * 64 + lr0] = m0r;
        g_part_m[unit * 64 + lr1] = m1r;
        g_part_l[unit * 64 + lr0] = l0;
        g_part_l[unit * 64 + lr1] = l1;
    }
#pragma unroll
    for (int nt = 0; nt < 8; nt++) {
        const int c = nt * 8 + 2 * tig;
        *(float2*)&g_part_o[((size_t)(unit * 64 + lr0)) * HS + c] =
            make_float2(oacc[nt][0], oacc[nt][1]);
        *(float2*)&g_part_o[((size_t)(unit * 64 + lr1)) * HS + c] =
            make_float2(oacc[nt][2], oacc[nt][3]);
    }
}

// ---------------- combine split-K partials (4 threads per row) --------------
__global__ __launch_bounds__(256) void attn_combine(float* __restrict__ out) {
    const int gid = blockIdx.x * 256 + threadIdx.x;   // 0..65535
    const int row = gid >> 2;                         // 0..16383 (b*2048+t)
    const int part = gid & 3;                         // 16-float slice of HS
    const int b = row >> 11;
    const int t = row & 2047;
    const int qb = t >> 6;
    const int lane = t & 63;
    const int nchunk = (qb + 1 + 7) / 8;              // 1..4 active chunks
    const int base_unit = (b * 32 + qb) * 4;

    float M = -INFINITY;
#pragma unroll 4
    for (int c = 0; c < nchunk; c++)
        M = fmaxf(M, g_part_m[(base_unit + c) * 64 + lane]);

    float w[4];
    float L = 0.f;
#pragma unroll 4
    for (int c = 0; c < nchunk; c++) {
        float wm = __expf(g_part_m[(base_unit + c) * 64 + lane] - M);
        w[c] = wm;
        L += wm * g_part_l[(base_unit + c) * 64 + lane];
    }
    const float inv = 1.f / L;

    float* op = out + (size_t)row * HS + part * 16;
#pragma unroll
    for (int i = 0; i < 4; i++) {
        float4 acc = make_float4(0.f, 0.f, 0.f, 0.f);
#pragma unroll 4
        for (int c = 0; c < nchunk; c++) {
            const float* po = g_part_o + ((size_t)((base_unit + c) * 64 + lane)) * HS
                            + part * 16;
            float4 v = *(const float4*)&po[i * 4];
            acc.x += w[c] * v.x; acc.y += w[c] * v.y;
            acc.z += w[c] * v.z; acc.w += w[c] * v.w;
        }
        acc.x *= inv; acc.y *= inv; acc.z *= inv; acc.w *= inv;
        *(float4*)&op[i * 4] = acc;
    }
}

// ---------------- launch ----------------------------------------------------
extern "C" void kernel_launch(void* const* d_in, const int* in_sizes, int n_in,
                              void* d_out, int out_size) {
    const float* x  = (const float*)d_in[0];
    const float* Wk = (const float*)d_in[1];
    const float* Wq = (const float*)d_in[2];
    const float* Wv = (const float*)d_in[3];
    float* out = (float*)d_out;

    qkv_gemm_tc<<<dim3(MROWS / 128, 3), 128>>>(x, Wk, Wq, Wv);
    attn_partial_tc<<<dim3(4, 32, BATCH), 128>>>();
    attn_combine<<<dim3(MROWS * 4 / 256), 256>>>(out);
}

// round 13
// speedup vs baseline: 1.2058x; 1.1011x over previous
#include <cuda_runtime.h>
#include <math.h>
#include <stdint.h>

#define TOK   2048
#define BATCH 8
#define NEMBD 768
#define HS    64
#define MROWS (BATCH*TOK)          // 16384

// ---------------- scratch (device globals; no allocation allowed) ----------
// q/k/v hold tf32-converted bits (q pre-scaled by 1/8)
static __device__ uint32_t g_q[MROWS*HS];
static __device__ uint32_t g_k[MROWS*HS];
static __device__ uint32_t g_v[MROWS*HS];

// split-K partials: unit = ((b*32 + qb)*4 + chunk), 1024 units x 64 rows
static __device__ float g_part_o[1024*64*HS];
static __device__ float g_part_m[1024*64];
static __device__ float g_part_l[1024*64];

// ---------------- helpers ---------------------------------------------------
__device__ __forceinline__ uint32_t f2tf32(float f) {
    uint32_t u;
    asm("cvt.rna.tf32.f32 %0, %1;" : "=r"(u) : "f"(f));
    return u;
}
__device__ __forceinline__ uint32_t u2tf32(uint32_t bits) {
    return f2tf32(__uint_as_float(bits));
}

__device__ __forceinline__ void mma_tf32(float c[4],
                                         uint32_t a0, uint32_t a1, uint32_t a2, uint32_t a3,
                                         uint32_t b0, uint32_t b1) {
    asm volatile(
        "mma.sync.aligned.m16n8k8.row.col.f32.tf32.tf32.f32 "
        "{%0,%1,%2,%3},{%4,%5,%6,%7},{%8,%9},{%0,%1,%2,%3};"
        : "+f"(c[0]), "+f"(c[1]), "+f"(c[2]), "+f"(c[3])
        : "r"(a0), "r"(a1), "r"(a2), "r"(a3), "r"(b0), "r"(b1));
}

__device__ __forceinline__ void cp_async16(uint32_t dst_smem, const void* src) {
    asm volatile("cp.async.cg.shared.global [%0], [%1], 16;"
                 :: "r"(dst_smem), "l"(src));
}
__device__ __forceinline__ uint32_t smem_u32(const void* p) {
    return (uint32_t)__cvta_generic_to_shared(p);
}

// ---------------- QKV projection: out[M,64] = x[M,768] @ W[768,64] ---------
// block = 128 threads (4 warps), tile 128 rows x 64 cols, BK = 16, 3-stage cp.async
// (round-7 proven version: 55.1us)
#define ASTQ 20
#define BSTQ 72
#define KT   48    // 768/16 BK-iterations
__global__ __launch_bounds__(128) void qkv_gemm_tc(const float* __restrict__ x,
                                                   const float* __restrict__ Wk,
                                                   const float* __restrict__ Wq,
                                                   const float* __restrict__ Wv) {
    __shared__ uint32_t As[3][128 * ASTQ];   // raw fp32 bits
    __shared__ uint32_t Bs[3][16 * BSTQ];

    const float* W;
    uint32_t* out;
    float oscale;
    if (blockIdx.y == 0)      { W = Wq; out = g_q; oscale = 0.125f; }
    else if (blockIdx.y == 1) { W = Wk; out = g_k; oscale = 1.0f; }
    else                      { W = Wv; out = g_v; oscale = 1.0f; }

    const int tid  = threadIdx.x;
    const int warp = tid >> 5;
    const int lane = tid & 31;
    const int g    = lane >> 2;
    const int tig  = lane & 3;
    const int row0 = blockIdx.x * 128;

    const int ar = tid >> 2;            // A row for i=0 (rows ar, ar+32, ...)
    const int ac = (tid & 3) * 4;
    const int br = tid >> 4;
    const int bc = (tid & 15) * 4;

    float acc[2][8][4];
#pragma unroll
    for (int mt = 0; mt < 2; mt++)
#pragma unroll
        for (int nt = 0; nt < 8; nt++)
#pragma unroll
            for (int i = 0; i < 4; i++) acc[mt][nt][i] = 0.f;

#define QKV_ISSUE(s, k0)                                                          \
    do {                                                                          \
        _Pragma("unroll")                                                         \
        for (int i = 0; i < 4; i++) {                                             \
            int r = ar + i * 32;                                                  \
            cp_async16(smem_u32(&As[s][r * ASTQ + ac]),                           \
                       &x[(size_t)(row0 + r) * NEMBD + (k0) + ac]);               \
        }                                                                         \
        _Pragma("unroll")                                                         \
        for (int i = 0; i < 2; i++) {                                             \
            int r = br + i * 8;                                                   \
            cp_async16(smem_u32(&Bs[s][r * BSTQ + bc]),                           \
                       &W[(size_t)((k0) + r) * HS + bc]);                         \
        }                                                                         \
        asm volatile("cp.async.commit_group;");                                   \
    } while (0)

    QKV_ISSUE(0, 0);
    QKV_ISSUE(1, 16);

    for (int it = 0; it < KT; it++) {
        if (it == KT - 1) asm volatile("cp.async.wait_group 0;");
        else              asm volatile("cp.async.wait_group 1;");
        __syncthreads();

        if (it + 2 < KT) QKV_ISSUE((it + 2) % 3, (it + 2) * 16);

        const uint32_t* as = As[it % 3];
        const uint32_t* bs = Bs[it % 3];

#pragma unroll
        for (int kk = 0; kk < 2; kk++) {
            uint32_t af[2][4];
#pragma unroll
            for (int mt = 0; mt < 2; mt++) {
                const int m0 = warp * 32 + mt * 16;
                af[mt][0] = u2tf32(as[(m0 + g) * ASTQ + kk * 8 + tig]);
                af[mt][1] = u2tf32(as[(m0 + g + 8) * ASTQ + kk * 8 + tig]);
                af[mt][2] = u2tf32(as[(m0 + g) * ASTQ + kk * 8 + tig + 4]);
                af[mt][3] = u2tf32(as[(m0 + g + 8) * ASTQ + kk * 8 + tig + 4]);
            }
#pragma unroll
            for (int nt = 0; nt < 8; nt++) {
                uint32_t b0 = u2tf32(bs[(kk * 8 + tig) * BSTQ + nt * 8 + g]);
                uint32_t b1 = u2tf32(bs[(kk * 8 + tig + 4) * BSTQ + nt * 8 + g]);
                mma_tf32(acc[0][nt], af[0][0], af[0][1], af[0][2], af[0][3], b0, b1);
                mma_tf32(acc[1][nt], af[1][0], af[1][1], af[1][2], af[1][3], b0, b1);
            }
        }
    }

    // epilogue: scale (Q only) + convert to tf32 bits
#pragma unroll
    for (int mt = 0; mt < 2; mt++) {
        const int r0 = row0 + warp * 32 + mt * 16 + g;
#pragma unroll
        for (int nt = 0; nt < 8; nt++) {
            const int c = nt * 8 + 2 * tig;
            *(uint2*)&out[(size_t)r0 * HS + c] =
                make_uint2(f2tf32(acc[mt][nt][0] * oscale), f2tf32(acc[mt][nt][1] * oscale));
            *(uint2*)&out[(size_t)(r0 + 8) * HS + c] =
                make_uint2(f2tf32(acc[mt][nt][2] * oscale), f2tf32(acc[mt][nt][3] * oscale));
        }
    }
}

// ---------------- flash attention partial (tensor cores, split along keys) --
// grid = (4 chunks, 32 qblocks, 8 batches), 128 threads (4 warps)
// cp.async pipeline: K double-buffered (hidden behind full prev tile),
// V single-buffered (issued at tile top, waited after S+softmax).
// Dynamic smem: 2*64*KSTK + 64*KSTV words = 53248 bytes (4 CTAs/SM kept).
#define KSTK 68
#define KSTV 72
#define KW   (64 * KSTK)
#define ATTN_SMEM_BYTES ((2 * KW + 64 * KSTV) * 4)
__global__ __launch_bounds__(128) void attn_partial_tc() {
    extern __shared__ uint32_t dsm[];
    uint32_t* const Kb0 = dsm;
    uint32_t* const Kb1 = dsm + KW;
    uint32_t* const Vsh = dsm + 2 * KW;

    const int chunk = blockIdx.x;
    const int qb    = blockIdx.y;        // 0..31, 64 rows each
    const int b     = blockIdx.z;

    const int nkb = qb + 1;              // 64-key tiles needed (causal)
    const int kb0 = chunk * 8;
    if (kb0 >= nkb) return;
    const int kb1 = (kb0 + 8 < nkb) ? kb0 + 8 : nkb;

    const int tid  = threadIdx.x;
    const int warp = tid >> 5;
    const int lane = tid & 31;
    const int g    = lane >> 2;
    const int tig  = lane & 3;
    const int qrow0 = qb * 64;           // block's first q row (within batch)

#define ATTN_ISSUE_K(buf, kb_)                                                    \
    do {                                                                          \
        _Pragma("unroll")                                                         \
        for (int i = 0; i < 8; i++) {                                             \
            int idx = tid + i * 128;                                              \
            int r   = idx >> 4;                                                   \
            int c4  = (idx & 15) * 4;                                             \
            cp_async16(smem_u32(&(buf)[r * KSTK + c4]),                           \
                       &g_k[((size_t)(b * TOK + (kb_) * 64 + r)) * HS + c4]);     \
        }                                                                         \
        asm volatile("cp.async.commit_group;");                                   \
    } while (0)

#define ATTN_ISSUE_V(kb_)                                                         \
    do {                                                                          \
        _Pragma("unroll")                                                         \
        for (int i = 0; i < 8; i++) {                                             \
            int idx = tid + i * 128;                                              \
            int r   = idx >> 4;                                                   \
            int c4  = (idx & 15) * 4;                                             \
            cp_async16(smem_u32(&Vsh[r * KSTV + c4]),                             \
                       &g_v[((size_t)(b * TOK + (kb_) * 64 + r)) * HS + c4]);     \
        }                                                                         \
        asm volatile("cp.async.commit_group;");                                   \
    } while (0)

    // prologue: first K tile in flight while we stage Q
    ATTN_ISSUE_K(Kb0, kb0);

    // ---- stage Q (already tf32+scaled) through Vsh, pull fragments ---------
#pragma unroll
    for (int i = 0; i < 8; i++) {
        int idx = tid + i * 128;
        int r   = idx >> 4;
        int c4  = (idx & 15) * 4;
        *(uint4*)&Vsh[r * KSTV + c4] =
            *(const uint4*)&g_q[((size_t)(b * TOK + qrow0 + r)) * HS + c4];
    }
    __syncthreads();

    uint32_t qf[8][4];
    const int mrow = warp * 16;          // warp's first local row
#pragma unroll
    for (int ks = 0; ks < 8; ks++) {
        qf[ks][0] = Vsh[(mrow + g) * KSTV + ks * 8 + tig];
        qf[ks][1] = Vsh[(mrow + g + 8) * KSTV + ks * 8 + tig];
        qf[ks][2] = Vsh[(mrow + g) * KSTV + ks * 8 + tig + 4];
        qf[ks][3] = Vsh[(mrow + g + 8) * KSTV + ks * 8 + tig + 4];
    }
    __syncthreads();

    float oacc[8][4];
#pragma unroll
    for (int nt = 0; nt < 8; nt++)
#pragma unroll
        for (int i = 0; i < 4; i++) oacc[nt][i] = 0.f;

    float m0r = -INFINITY, m1r = -INFINITY;   // rows g and g+8
    float l0 = 0.f, l1 = 0.f;

    const int rg0 = qrow0 + mrow + g;         // global (in-batch) q rows
    const int rg1 = rg0 + 8;

    // shuffle sources for C-frag -> A-frag redistribution
    const int src0 = (lane & ~3) | (tig >> 1);
    const int src1 = src0 + 2;
    const bool odd = (tig & 1);

    int it = 0;
    for (int kb = kb0; kb < kb1; kb++, it++) {
        const uint32_t* Kc = (it & 1) ? Kb1 : Kb0;
        const bool hn = (kb + 1 < kb1);

        // drain K for this tile (issued one tile ago -> latency hidden)
        asm volatile("cp.async.wait_group 0;");
        __syncthreads();   // K visible to all; also: all warps done prev PV (Vsh reusable)

        ATTN_ISSUE_V(kb);                                   // group: V_i
        if (hn) {
            if (it & 1) ATTN_ISSUE_K(Kb0, kb + 1);          // group: K_{i+1}
            else        ATTN_ISSUE_K(Kb1, kb + 1);
        }

        // ---- S = Q K^T (16 x 64 per warp) ---------------------------------
        float sacc[8][4];
#pragma unroll
        for (int nt = 0; nt < 8; nt++) {
#pragma unroll
            for (int i = 0; i < 4; i++) sacc[nt][i] = 0.f;
#pragma unroll
            for (int ks = 0; ks < 8; ks++) {
                uint32_t b0 = Kc[(nt * 8 + g) * KSTK + ks * 8 + tig];
                uint32_t b1 = Kc[(nt * 8 + g) * KSTK + ks * 8 + tig + 4];
                mma_tf32(sacc[nt], qf[ks][0], qf[ks][1], qf[ks][2], qf[ks][3], b0, b1);
            }
        }

        // ---- causal mask (only the diagonal tile can clip) ----------------
        if (kb == qb) {
            const int colbase = kb * 64;
#pragma unroll
            for (int nt = 0; nt < 8; nt++) {
                const int c0 = colbase + nt * 8 + 2 * tig;
                if (c0 > rg0)     sacc[nt][0] = -INFINITY;
                if (c0 + 1 > rg0) sacc[nt][1] = -INFINITY;
                if (c0 > rg1)     sacc[nt][2] = -INFINITY;
                if (c0 + 1 > rg1) sacc[nt][3] = -INFINITY;
            }
        }

        // ---- online softmax -----------------------------------------------
        float mx0 = -INFINITY, mx1 = -INFINITY;
#pragma unroll
        for (int nt = 0; nt < 8; nt++) {
            mx0 = fmaxf(mx0, fmaxf(sacc[nt][0], sacc[nt][1]));
            mx1 = fmaxf(mx1, fmaxf(sacc[nt][2], sacc[nt][3]));
        }
        mx0 = fmaxf(mx0, __shfl_xor_sync(0xffffffffu, mx0, 1));
        mx0 = fmaxf(mx0, __shfl_xor_sync(0xffffffffu, mx0, 2));
        mx1 = fmaxf(mx1, __shfl_xor_sync(0xffffffffu, mx1, 1));
        mx1 = fmaxf(mx1, __shfl_xor_sync(0xffffffffu, mx1, 2));

        const float mn0 = fmaxf(m0r, mx0);
        const float mn1 = fmaxf(m1r, mx1);
        const float alpha0 = __expf(m0r - mn0);   // first iter: exp(-inf)=0
        const float alpha1 = __expf(m1r - mn1);
        m0r = mn0; m1r = mn1;

        float ps0 = 0.f, ps1 = 0.f;
#pragma unroll
        for (int nt = 0; nt < 8; nt++) {
            sacc[nt][0] = __expf(sacc[nt][0] - mn0);
            sacc[nt][1] = __expf(sacc[nt][1] - mn0);
            sacc[nt][2] = __expf(sacc[nt][2] - mn1);
            sacc[nt][3] = __expf(sacc[nt][3] - mn1);
            ps0 += sacc[nt][0] + sacc[nt][1];
            ps1 += sacc[nt][2] + sacc[nt][3];
        }
        ps0 += __shfl_xor_sync(0xffffffffu, ps0, 1);
        ps0 += __shfl_xor_sync(0xffffffffu, ps0, 2);
        ps1 += __shfl_xor_sync(0xffffffffu, ps1, 1);
        ps1 += __shfl_xor_sync(0xffffffffu, ps1, 2);
        l0 = l0 * alpha0 + ps0;
        l1 = l1 * alpha1 + ps1;

#pragma unroll
        for (int nt = 0; nt < 8; nt++) {
            oacc[nt][0] *= alpha0; oacc[nt][1] *= alpha0;
            oacc[nt][2] *= alpha1; oacc[nt][3] *= alpha1;
        }

        // drain V (issued at tile top -> hidden behind S+softmax)
        if (hn) asm volatile("cp.async.wait_group 1;");
        else    asm volatile("cp.async.wait_group 0;");
        __syncthreads();

        // ---- O += P V : P redistributed C-frag -> A-frag via shuffles ------
#pragma unroll
        for (int ks = 0; ks < 8; ks++) {
            const float p0a = __shfl_sync(0xffffffffu, sacc[ks][0], src0);
            const float p1a = __shfl_sync(0xffffffffu, sacc[ks][1], src0);
            const float p2a = __shfl_sync(0xffffffffu, sacc[ks][2], src0);
            const float p3a = __shfl_sync(0xffffffffu, sacc[ks][3], src0);
            const float p0b = __shfl_sync(0xffffffffu, sacc[ks][0], src1);
            const float p1b = __shfl_sync(0xffffffffu, sacc[ks][1], src1);
            const float p2b = __shfl_sync(0xffffffffu, sacc[ks][2], src1);
            const float p3b = __shfl_sync(0xffffffffu, sacc[ks][3], src1);
            const uint32_t pa0 = f2tf32(odd ? p1a : p0a);
            const uint32_t pa1 = f2tf32(odd ? p3a : p2a);
            const uint32_t pa2 = f2tf32(odd ? p1b : p0b);
            const uint32_t pa3 = f2tf32(odd ? p3b : p2b);
#pragma unroll
            for (int nt = 0; nt < 8; nt++) {
                uint32_t b0 = Vsh[(ks * 8 + tig) * KSTV + nt * 8 + g];
                uint32_t b1 = Vsh[(ks * 8 + tig + 4) * KSTV + nt * 8 + g];
                mma_tf32(oacc[nt], pa0, pa1, pa2, pa3, b0, b1);
            }
        }
        // no trailing sync: next iteration's top sync protects Vsh/K buffers
    }

    // ---- write partials ----------------------------------------------------
    const int unit = (b * 32 + qb) * 4 + chunk;
    const int lr0 = mrow + g;            // local rows within 64
    const int lr1 = lr0 + 8;
    if (tig == 0) {
        g_part_m[unit * 64 + lr0] = m0r;
        g_part_m[unit * 64 + lr1] = m1r;
        g_part_l[unit * 64 + lr0] = l0;
        g_part_l[unit * 64 + lr1] = l1;
    }
#pragma unroll
    for (int nt = 0; nt < 8; nt++) {
        const int c = nt * 8 + 2 * tig;
        *(float2*)&g_part_o[((size_t)(unit * 64 + lr0)) * HS + c] =
            make_float2(oacc[nt][0], oacc[nt][1]);
        *(float2*)&g_part_o[((size_t)(unit * 64 + lr1)) * HS + c] =
            make_float2(oacc[nt][2], oacc[nt][3]);
    }
}

// ---------------- combine split-K partials (4 threads per row) --------------
__global__ __launch_bounds__(256) void attn_combine(float* __restrict__ out) {
    const int gid = blockIdx.x * 256 + threadIdx.x;   // 0..65535
    const int row = gid >> 2;                         // 0..16383 (b*2048+t)
    const int part = gid & 3;                         // 16-float slice of HS
    const int b = row >> 11;
    const int t = row & 2047;
    const int qb = t >> 6;
    const int lane = t & 63;
    const int nchunk = (qb + 1 + 7) / 8;              // 1..4 active chunks
    const int base_unit = (b * 32 + qb) * 4;

    float M = -INFINITY;
#pragma unroll 4
    for (int c = 0; c < nchunk; c++)
        M = fmaxf(M, g_part_m[(base_unit + c) * 64 + lane]);

    float w[4];
    float L = 0.f;
#pragma unroll 4
    for (int c = 0; c < nchunk; c++) {
        float wm = __expf(g_part_m[(base_unit + c) * 64 + lane] - M);
        w[c] = wm;
        L += wm * g_part_l[(base_unit + c) * 64 + lane];
    }
    const float inv = 1.f / L;

    float* op = out + (size_t)row * HS + part * 16;
#pragma unroll
    for (int i = 0; i < 4; i++) {
        float4 acc = make_float4(0.f, 0.f, 0.f, 0.f);
#pragma unroll 4
        for (int c = 0; c < nchunk; c++) {
            const float* po = g_part_o + ((size_t)((base_unit + c) * 64 + lane)) * HS
                            + part * 16;
            float4 v = *(const float4*)&po[i * 4];
            acc.x += w[c] * v.x; acc.y += w[c] * v.y;
            acc.z += w[c] * v.z; acc.w += w[c] * v.w;
        }
        acc.x *= inv; acc.y *= inv; acc.z *= inv; acc.w *= inv;
        *(float4*)&op[i * 4] = acc;
    }
}

// ---------------- launch ----------------------------------------------------
extern "C" void kernel_launch(void* const* d_in, const int* in_sizes, int n_in,
                              void* d_out, int out_size) {
    const float* x  = (const float*)d_in[0];
    const float* Wk = (const float*)d_in[1];
    const float* Wq = (const float*)d_in[2];
    const float* Wv = (const float*)d_in[3];
    float* out = (float*)d_out;

    cudaFuncSetAttribute(attn_partial_tc,
                         cudaFuncAttributeMaxDynamicSharedMemorySize,
                         ATTN_SMEM_BYTES);

    qkv_gemm_tc<<<dim3(MROWS / 128, 3), 128>>>(x, Wk, Wq, Wv);
    attn_partial_tc<<<dim3(4, 32, BATCH), 128, ATTN_SMEM_BYTES>>>();
    attn_combine<<<dim3(MROWS * 4 / 256), 256>>>(out);
}

// round 15
// speedup vs baseline: 1.2258x; 1.0165x over previous
#include <cuda_runtime.h>
#include <math.h>
#include <stdint.h>

#define TOK   2048
#define BATCH 8
#define NEMBD 768
#define HS    64
#define MROWS (BATCH*TOK)          // 16384

// ---------------- scratch (device globals; no allocation allowed) ----------
// q/k/v hold tf32-converted bits (q pre-scaled by 1/8)
static __device__ uint32_t g_q[MROWS*HS];
static __device__ uint32_t g_k[MROWS*HS];
static __device__ uint32_t g_v[MROWS*HS];
// pre-converted weights (tf32 bits): [Wq | Wk | Wv]
static __device__ uint32_t g_wt[3*NEMBD*HS];

// split-K partials: unit = ((b*32 + qb)*4 + chunk), 1024 units x 64 rows
static __device__ float g_part_o[1024*64*HS];
static __device__ float g_part_m[1024*64];
static __device__ float g_part_l[1024*64];

// ---------------- helpers ---------------------------------------------------
__device__ __forceinline__ uint32_t f2tf32(float f) {
    uint32_t u;
    asm("cvt.rna.tf32.f32 %0, %1;" : "=r"(u) : "f"(f));
    return u;
}
__device__ __forceinline__ uint32_t u2tf32(uint32_t bits) {
    return f2tf32(__uint_as_float(bits));
}

__device__ __forceinline__ void mma_tf32(float c[4],
                                         uint32_t a0, uint32_t a1, uint32_t a2, uint32_t a3,
                                         uint32_t b0, uint32_t b1) {
    asm volatile(
        "mma.sync.aligned.m16n8k8.row.col.f32.tf32.tf32.f32 "
        "{%0,%1,%2,%3},{%4,%5,%6,%7},{%8,%9},{%0,%1,%2,%3};"
        : "+f"(c[0]), "+f"(c[1]), "+f"(c[2]), "+f"(c[3])
        : "r"(a0), "r"(a1), "r"(a2), "r"(a3), "r"(b0), "r"(b1));
}

__device__ __forceinline__ void cp_async16(uint32_t dst_smem, const void* src) {
    asm volatile("cp.async.cg.shared.global [%0], [%1], 16;"
                 :: "r"(dst_smem), "l"(src));
}
__device__ __forceinline__ uint32_t smem_u32(const void* p) {
    return (uint32_t)__cvta_generic_to_shared(p);
}

// ---------------- weight pre-conversion: fp32 -> tf32 bits ------------------
__global__ __launch_bounds__(256) void w_convert(const float* __restrict__ Wq,
                                                 const float* __restrict__ Wk,
                                                 const float* __restrict__ Wv) {
    const int i4 = blockIdx.x * 256 + threadIdx.x;     // uint4 index, 0..36863
    const int per = NEMBD * HS / 4;                    // 12288 float4 per matrix
    const float* src = (i4 < per) ? Wq : (i4 < 2 * per) ? Wk : Wv;
    const int off = (i4 % per) * 4;
    float4 w = *(const float4*)&src[off];
    *(uint4*)&g_wt[(i4 / per) * NEMBD * HS + off] =
        make_uint4(f2tf32(w.x), f2tf32(w.y), f2tf32(w.z), f2tf32(w.w));
}

// ---------------- QKV projection: out[M,64] = x[M,768] @ W[768,64] ---------
// block = 128 threads (4 warps), tile 128 rows x 64 cols, BK = 16, 3-stage cp.async
// Identical structure to the proven 54us version; B side is pre-converted tf32
// (g_wt) so B fragments need no cvt (-32 cvt/thread/iter).
#define ASTQ 20
#define BSTQ 72
#define KT   48    // 768/16 BK-iterations
__global__ __launch_bounds__(128) void qkv_gemm_tc(const float* __restrict__ x) {
    __shared__ uint32_t As[3][128 * ASTQ];   // raw fp32 bits
    __shared__ uint32_t Bs[3][16 * BSTQ];    // tf32 bits (pre-converted)

    const uint32_t* W = g_wt + blockIdx.y * (NEMBD * HS);
    uint32_t* out;
    float oscale;
    if (blockIdx.y == 0)      { out = g_q; oscale = 0.125f; }
    else if (blockIdx.y == 1) { out = g_k; oscale = 1.0f; }
    else                      { out = g_v; oscale = 1.0f; }

    const int tid  = threadIdx.x;
    const int warp = tid >> 5;
    const int lane = tid & 31;
    const int g    = lane >> 2;
    const int tig  = lane & 3;
    const int row0 = blockIdx.x * 128;

    const int ar = tid >> 2;            // A row for i=0 (rows ar, ar+32, ...)
    const int ac = (tid & 3) * 4;
    const int br = tid >> 4;
    const int bc = (tid & 15) * 4;

    float acc[2][8][4];
#pragma unroll
    for (int mt = 0; mt < 2; mt++)
#pragma unroll
        for (int nt = 0; nt < 8; nt++)
#pragma unroll
            for (int i = 0; i < 4; i++) acc[mt][nt][i] = 0.f;

#define QKV_ISSUE(s, k0)                                                          \
    do {                                                                          \
        _Pragma("unroll")                                                         \
        for (int i = 0; i < 4; i++) {                                             \
            int r = ar + i * 32;                                                  \
            cp_async16(smem_u32(&As[s][r * ASTQ + ac]),                           \
                       &x[(size_t)(row0 + r) * NEMBD + (k0) + ac]);               \
        }                                                                         \
        _Pragma("unroll")                                                         \
        for (int i = 0; i < 2; i++) {                                             \
            int r = br + i * 8;                                                   \
            cp_async16(smem_u32(&Bs[s][r * BSTQ + bc]),                           \
                       &W[(size_t)((k0) + r) * HS + bc]);                         \
        }                                                                         \
        asm volatile("cp.async.commit_group;");                                   \
    } while (0)

    QKV_ISSUE(0, 0);
    QKV_ISSUE(1, 16);

    for (int it = 0; it < KT; it++) {
        if (it == KT - 1) asm volatile("cp.async.wait_group 0;");
        else              asm volatile("cp.async.wait_group 1;");
        __syncthreads();

        if (it + 2 < KT) QKV_ISSUE((it + 2) % 3, (it + 2) * 16);

        const uint32_t* as = As[it % 3];
        const uint32_t* bs = Bs[it % 3];

#pragma unroll
        for (int kk = 0; kk < 2; kk++) {
            uint32_t af[2][4];
#pragma unroll
            for (int mt = 0; mt < 2; mt++) {
                const int m0 = warp * 32 + mt * 16;
                af[mt][0] = u2tf32(as[(m0 + g) * ASTQ + kk * 8 + tig]);
                af[mt][1] = u2tf32(as[(m0 + g + 8) * ASTQ + kk * 8 + tig]);
                af[mt][2] = u2tf32(as[(m0 + g) * ASTQ + kk * 8 + tig + 4]);
                af[mt][3] = u2tf32(as[(m0 + g + 8) * ASTQ + kk * 8 + tig + 4]);
            }
#pragma unroll
            for (int nt = 0; nt < 8; nt++) {
                uint32_t b0 = bs[(kk * 8 + tig) * BSTQ + nt * 8 + g];
                uint32_t b1 = bs[(kk * 8 + tig + 4) * BSTQ + nt * 8 + g];
                mma_tf32(acc[0][nt], af[0][0], af[0][1], af[0][2], af[0][3], b0, b1);
                mma_tf32(acc[1][nt], af[1][0], af[1][1], af[1][2], af[1][3], b0, b1);
            }
        }
    }

    // epilogue: scale (Q only) + convert to tf32 bits
#pragma unroll
    for (int mt = 0; mt < 2; mt++) {
        const int r0 = row0 + warp * 32 + mt * 16 + g;
#pragma unroll
        for (int nt = 0; nt < 8; nt++) {
            const int c = nt * 8 + 2 * tig;
            *(uint2*)&out[(size_t)r0 * HS + c] =
                make_uint2(f2tf32(acc[mt][nt][0] * oscale), f2tf32(acc[mt][nt][1] * oscale));
            *(uint2*)&out[(size_t)(r0 + 8) * HS + c] =
                make_uint2(f2tf32(acc[mt][nt][2] * oscale), f2tf32(acc[mt][nt][3] * oscale));
        }
    }
}

// ---------------- flash attention partial (tensor cores, split along keys) --
// grid = (4 chunks, 32 qblocks, 8 batches), 128 threads (4 warps)
// cp.async pipeline: K double-buffered, V single-buffered (proven R13: ~52us)
#define KSTK 68
#define KSTV 72
#define KW   (64 * KSTK)
#define ATTN_SMEM_BYTES ((2 * KW + 64 * KSTV) * 4)
__global__ __launch_bounds__(128) void attn_partial_tc() {
    extern __shared__ uint32_t dsm[];
    uint32_t* const Kb0 = dsm;
    uint32_t* const Kb1 = dsm + KW;
    uint32_t* const Vsh = dsm + 2 * KW;

    const int chunk = blockIdx.x;
    const int qb    = blockIdx.y;        // 0..31, 64 rows each
    const int b     = blockIdx.z;

    const int nkb = qb + 1;              // 64-key tiles needed (causal)
    const int kb0 = chunk * 8;
    if (kb0 >= nkb) return;
    const int kb1 = (kb0 + 8 < nkb) ? kb0 + 8 : nkb;

    const int tid  = threadIdx.x;
    const int warp = tid >> 5;
    const int lane = tid & 31;
    const int g    = lane >> 2;
    const int tig  = lane & 3;
    const int qrow0 = qb * 64;           // block's first q row (within batch)

#define ATTN_ISSUE_K(buf, kb_)                                                    \
    do {                                                                          \
        _Pragma("unroll")                                                         \
        for (int i = 0; i < 8; i++) {                                             \
            int idx = tid + i * 128;                                              \
            int r   = idx >> 4;                                                   \
            int c4  = (idx & 15) * 4;                                             \
            cp_async16(smem_u32(&(buf)[r * KSTK + c4]),                           \
                       &g_k[((size_t)(b * TOK + (kb_) * 64 + r)) * HS + c4]);     \
        }                                                                         \
        asm volatile("cp.async.commit_group;");                                   \
    } while (0)

#define ATTN_ISSUE_V(kb_)                                                         \
    do {                                                                          \
        _Pragma("unroll")                                                         \
        for (int i = 0; i < 8; i++) {                                             \
            int idx = tid + i * 128;                                              \
            int r   = idx >> 4;                                                   \
            int c4  = (idx & 15) * 4;                                             \
            cp_async16(smem_u32(&Vsh[r * KSTV + c4]),                             \
                       &g_v[((size_t)(b * TOK + (kb_) * 64 + r)) * HS + c4]);     \
        }                                                                         \
        asm volatile("cp.async.commit_group;");                                   \
    } while (0)

    // prologue: first K tile in flight while we stage Q
    ATTN_ISSUE_K(Kb0, kb0);

    // ---- stage Q (already tf32+scaled) through Vsh, pull fragments ---------
#pragma unroll
    for (int i = 0; i < 8; i++) {
        int idx = tid + i * 128;
        int r   = idx >> 4;
        int c4  = (idx & 15) * 4;
        *(uint4*)&Vsh[r * KSTV + c4] =
            *(const uint4*)&g_q[((size_t)(b * TOK + qrow0 + r)) * HS + c4];
    }
    __syncthreads();

    uint32_t qf[8][4];
    const int mrow = warp * 16;          // warp's first local row
#pragma unroll
    for (int ks = 0; ks < 8; ks++) {
        qf[ks][0] = Vsh[(mrow + g) * KSTV + ks * 8 + tig];
        qf[ks][1] = Vsh[(mrow + g + 8) * KSTV + ks * 8 + tig];
        qf[ks][2] = Vsh[(mrow + g) * KSTV + ks * 8 + tig + 4];
        qf[ks][3] = Vsh[(mrow + g + 8) * KSTV + ks * 8 + tig + 4];
    }
    __syncthreads();

    float oacc[8][4];
#pragma unroll
    for (int nt = 0; nt < 8; nt++)
#pragma unroll
        for (int i = 0; i < 4; i++) oacc[nt][i] = 0.f;

    float m0r = -INFINITY, m1r = -INFINITY;   // rows g and g+8
    float l0 = 0.f, l1 = 0.f;

    const int rg0 = qrow0 + mrow + g;         // global (in-batch) q rows
    const int rg1 = rg0 + 8;

    // shuffle sources for C-frag -> A-frag redistribution
    const int src0 = (lane & ~3) | (tig >> 1);
    const int src1 = src0 + 2;
    const bool odd = (tig & 1);

    int it = 0;
    for (int kb = kb0; kb < kb1; kb++, it++) {
        const uint32_t* Kc = (it & 1) ? Kb1 : Kb0;
        const bool hn = (kb + 1 < kb1);

        // drain K for this tile (issued one tile ago -> latency hidden)
        asm volatile("cp.async.wait_group 0;");
        __syncthreads();   // K visible to all; also: all warps done prev PV (Vsh reusable)

        ATTN_ISSUE_V(kb);                                   // group: V_i
        if (hn) {
            if (it & 1) ATTN_ISSUE_K(Kb0, kb + 1);          // group: K_{i+1}
            else        ATTN_ISSUE_K(Kb1, kb + 1);
        }

        // ---- S = Q K^T (16 x 64 per warp) ---------------------------------
        float sacc[8][4];
#pragma unroll
        for (int nt = 0; nt < 8; nt++) {
#pragma unroll
            for (int i = 0; i < 4; i++) sacc[nt][i] = 0.f;
#pragma unroll
            for (int ks = 0; ks < 8; ks++) {
                uint32_t b0 = Kc[(nt * 8 + g) * KSTK + ks * 8 + tig];
                uint32_t b1 = Kc[(nt * 8 + g) * KSTK + ks * 8 + tig + 4];
                mma_tf32(sacc[nt], qf[ks][0], qf[ks][1], qf[ks][2], qf[ks][3], b0, b1);
            }
        }

        // ---- causal mask (only the diagonal tile can clip) ----------------
        if (kb == qb) {
            const int colbase = kb * 64;
#pragma unroll
            for (int nt = 0; nt < 8; nt++) {
                const int c0 = colbase + nt * 8 + 2 * tig;
                if (c0 > rg0)     sacc[nt][0] = -INFINITY;
                if (c0 + 1 > rg0) sacc[nt][1] = -INFINITY;
                if (c0 > rg1)     sacc[nt][2] = -INFINITY;
                if (c0 + 1 > rg1) sacc[nt][3] = -INFINITY;
            }
        }

        // ---- online softmax -----------------------------------------------
        float mx0 = -INFINITY, mx1 = -INFINITY;
#pragma unroll
        for (int nt = 0; nt < 8; nt++) {
            mx0 = fmaxf(mx0, fmaxf(sacc[nt][0], sacc[nt][1]));
            mx1 = fmaxf(mx1, fmaxf(sacc[nt][2], sacc[nt][3]));
        }
        mx0 = fmaxf(mx0, __shfl_xor_sync(0xffffffffu, mx0, 1));
        mx0 = fmaxf(mx0, __shfl_xor_sync(0xffffffffu, mx0, 2));
        mx1 = fmaxf(mx1, __shfl_xor_sync(0xffffffffu, mx1, 1));
        mx1 = fmaxf(mx1, __shfl_xor_sync(0xffffffffu, mx1, 2));

        const float mn0 = fmaxf(m0r, mx0);
        const float mn1 = fmaxf(m1r, mx1);
        const float alpha0 = __expf(m0r - mn0);   // first iter: exp(-inf)=0
        const float alpha1 = __expf(m1r - mn1);
        m0r = mn0; m1r = mn1;

        float ps0 = 0.f, ps1 = 0.f;
#pragma unroll
        for (int nt = 0; nt < 8; nt++) {
            sacc[nt][0] = __expf(sacc[nt][0] - mn0);
            sacc[nt][1] = __expf(sacc[nt][1] - mn0);
            sacc[nt][2] = __expf(sacc[nt][2] - mn1);
            sacc[nt][3] = __expf(sacc[nt][3] - mn1);
            ps0 += sacc[nt][0] + sacc[nt][1];
            ps1 += sacc[nt][2] + sacc[nt][3];
        }
        ps0 += __shfl_xor_sync(0xffffffffu, ps0, 1);
        ps0 += __shfl_xor_sync(0xffffffffu, ps0, 2);
        ps1 += __shfl_xor_sync(0xffffffffu, ps1, 1);
        ps1 += __shfl_xor_sync(0xffffffffu, ps1, 2);
        l0 = l0 * alpha0 + ps0;
        l1 = l1 * alpha1 + ps1;

#pragma unroll
        for (int nt = 0; nt < 8; nt++) {
            oacc[nt][0] *= alpha0; oacc[nt][1] *= alpha0;
            oacc[nt][2] *= alpha1; oacc[nt][3] *= alpha1;
        }

        // drain V (issued at tile top -> hidden behind S+softmax)
        if (hn) asm volatile("cp.async.wait_group 1;");
        else    asm volatile("cp.async.wait_group 0;");
        __syncthreads();

        // ---- O += P V : P redistributed C-frag -> A-frag via shuffles ------
#pragma unroll
        for (int ks = 0; ks < 8; ks++) {
            const float p0a = __shfl_sync(0xffffffffu, sacc[ks][0], src0);
            const float p1a = __shfl_sync(0xffffffffu, sacc[ks][1], src0);
            const float p2a = __shfl_sync(0xffffffffu, sacc[ks][2], src0);
            const float p3a = __shfl_sync(0xffffffffu, sacc[ks][3], src0);
            const float p0b = __shfl_sync(0xffffffffu, sacc[ks][0], src1);
            const float p1b = __shfl_sync(0xffffffffu, sacc[ks][1], src1);
            const float p2b = __shfl_sync(0xffffffffu, sacc[ks][2], src1);
            const float p3b = __shfl_sync(0xffffffffu, sacc[ks][3], src1);
            const uint32_t pa0 = f2tf32(odd ? p1a : p0a);
            const uint32_t pa1 = f2tf32(odd ? p3a : p2a);
            const uint32_t pa2 = f2tf32(odd ? p1b : p0b);
            const uint32_t pa3 = f2tf32(odd ? p3b : p2b);
#pragma unroll
            for (int nt = 0; nt < 8; nt++) {
                uint32_t b0 = Vsh[(ks * 8 + tig) * KSTV + nt * 8 + g];
                uint32_t b1 = Vsh[(ks * 8 + tig + 4) * KSTV + nt * 8 + g];
                mma_tf32(oacc[nt], pa0, pa1, pa2, pa3, b0, b1);
            }
        }
        // no trailing sync: next iteration's top sync protects Vsh/K buffers
    }

    // ---- write partials ----------------------------------------------------
    const int unit = (b * 32 + qb) * 4 + chunk;
    const int lr0 = mrow + g;            // local rows within 64
    const int lr1 = lr0 + 8;
    if (tig == 0) {
        g_part_m[unit * 64 + lr0] = m0r;
        g_part_m[unit * 64 + lr1] = m1r;
        g_part_l[unit * 64 + lr0] = l0;
        g_part_l[unit * 64 + lr1] = l1;
    }
#pragma unroll
    for (int nt = 0; nt < 8; nt++) {
        const int c = nt * 8 + 2 * tig;
        *(float2*)&g_part_o[((size_t)(unit * 64 + lr0)) * HS + c] =
            make_float2(oacc[nt][0], oacc[nt][1]);
        *(float2*)&g_part_o[((size_t)(unit * 64 + lr1)) * HS + c] =
            make_float2(oacc[nt][2], oacc[nt][3]);
    }
}

// ---------------- combine split-K partials (4 threads per row) --------------
__global__ __launch_bounds__(256) void attn_combine(float* __restrict__ out) {
    const int gid = blockIdx.x * 256 + threadIdx.x;   // 0..65535
    const int row = gid >> 2;                         // 0..16383 (b*2048+t)
    const int part = gid & 3;                         // 16-float slice of HS
    const int b = row >> 11;
    const int t = row & 2047;
    const int qb = t >> 6;
    const int lane = t & 63;
    const int nchunk = (qb + 1 + 7) / 8;              // 1..4 active chunks
    const int base_unit = (b * 32 + qb) * 4;

    float M = -INFINITY;
#pragma unroll 4
    for (int c = 0; c < nchunk; c++)
        M = fmaxf(M, g_part_m[(base_unit + c) * 64 + lane]);

    float w[4];
    float L = 0.f;
#pragma unroll 4
    for (int c = 0; c < nchunk; c++) {
        float wm = __expf(g_part_m[(base_unit + c) * 64 + lane] - M);
        w[c] = wm;
        L += wm * g_part_l[(base_unit + c) * 64 + lane];
    }
    const float inv = 1.f / L;

    float* op = out + (size_t)row * HS + part * 16;
#pragma unroll
    for (int i = 0; i < 4; i++) {
        float4 acc = make_float4(0.f, 0.f, 0.f, 0.f);
#pragma unroll 4
        for (int c = 0; c < nchunk; c++) {
            const float* po = g_part_o + ((size_t)((base_unit + c) * 64 + lane)) * HS
                            + part * 16;
            float4 v = *(const float4*)&po[i * 4];
            acc.x += w[c] * v.x; acc.y += w[c] * v.y;
            acc.z += w[c] * v.z; acc.w += w[c] * v.w;
        }
        acc.x *= inv; acc.y *= inv; acc.z *= inv; acc.w *= inv;
        *(float4*)&op[i * 4] = acc;
    }
}

// ---------------- launch ----------------------------------------------------
extern "C" void kernel_launch(void* const* d_in, const int* in_sizes, int n_in,
                              void* d_out, int out_size) {
    const float* x  = (const float*)d_in[0];
    const float* Wk = (const float*)d_in[1];
    const float* Wq = (const float*)d_in[2];
    const float* Wv = (const float*)d_in[3];
    float* out = (float*)d_out;

    cudaFuncSetAttribute(attn_partial_tc,
                         cudaFuncAttributeMaxDynamicSharedMemorySize,
                         ATTN_SMEM_BYTES);

    w_convert<<<dim3(3 * NEMBD * HS / 4 / 256), 256>>>(Wq, Wk, Wv);
    qkv_gemm_tc<<<dim3(MROWS / 128, 3), 128>>>(x);
    attn_partial_tc<<<dim3(4, 32, BATCH), 128, ATTN_SMEM_BYTES>>>();
    attn_combine<<<dim3(MROWS * 4 / 256), 256>>>(out);
}

// round 16
// speedup vs baseline: 1.2508x; 1.0204x over previous
#include <cuda_runtime.h>
#include <math.h>
#include <stdint.h>

#define TOK   2048
#define BATCH 8
#define NEMBD 768
#define HS    64
#define MROWS (BATCH*TOK)          // 16384

// ---------------- scratch (device globals; no allocation allowed) ----------
// q/k/v hold tf32-converted bits (q pre-scaled by 1/8)
static __device__ uint32_t g_q[MROWS*HS];
static __device__ uint32_t g_k[MROWS*HS];
static __device__ uint32_t g_v[MROWS*HS];
// pre-converted weights (tf32 bits): [Wq | Wk | Wv]
static __device__ uint32_t g_wt[3*NEMBD*HS];

// split-K partials: unit = ((b*32 + qb)*4 + chunk), 1024 units x 64 rows
static __device__ float g_part_o[1024*64*HS];
static __device__ float g_part_m[1024*64];
static __device__ float g_part_l[1024*64];

// ---------------- helpers ---------------------------------------------------
__device__ __forceinline__ uint32_t f2tf32(float f) {
    uint32_t u;
    asm("cvt.rna.tf32.f32 %0, %1;" : "=r"(u) : "f"(f));
    return u;
}
__device__ __forceinline__ uint32_t u2tf32(uint32_t bits) {
    return f2tf32(__uint_as_float(bits));
}

__device__ __forceinline__ void mma_tf32(float c[4],
                                         uint32_t a0, uint32_t a1, uint32_t a2, uint32_t a3,
                                         uint32_t b0, uint32_t b1) {
    asm volatile(
        "mma.sync.aligned.m16n8k8.row.col.f32.tf32.tf32.f32 "
        "{%0,%1,%2,%3},{%4,%5,%6,%7},{%8,%9},{%0,%1,%2,%3};"
        : "+f"(c[0]), "+f"(c[1]), "+f"(c[2]), "+f"(c[3])
        : "r"(a0), "r"(a1), "r"(a2), "r"(a3), "r"(b0), "r"(b1));
}

__device__ __forceinline__ void cp_async16(uint32_t dst_smem, const void* src) {
    asm volatile("cp.async.cg.shared.global [%0], [%1], 16;"
                 :: "r"(dst_smem), "l"(src));
}
__device__ __forceinline__ uint32_t smem_u32(const void* p) {
    return (uint32_t)__cvta_generic_to_shared(p);
}

// ---------------- weight pre-conversion: fp32 -> tf32 bits ------------------
__global__ __launch_bounds__(256) void w_convert(const float* __restrict__ Wq,
                                                 const float* __restrict__ Wk,
                                                 const float* __restrict__ Wv) {
    const int i4 = blockIdx.x * 256 + threadIdx.x;     // uint4 index, 0..36863
    const int per = NEMBD * HS / 4;                    // 12288 float4 per matrix
    const float* src = (i4 < per) ? Wq : (i4 < 2 * per) ? Wk : Wv;
    const int off = (i4 % per) * 4;
    float4 w = *(const float4*)&src[off];
    *(uint4*)&g_wt[(i4 / per) * NEMBD * HS + off] =
        make_uint4(f2tf32(w.x), f2tf32(w.y), f2tf32(w.z), f2tf32(w.w));
}

// ---------------- QKV projection: out[M,64] = x[M,768] @ W[768,64] ---------
// block = 128 threads (4 warps), tile 128 rows x 64 cols, BK = 16, 3-stage cp.async
// B side pre-converted tf32 (proven R15: ~46us)
#define ASTQ 20
#define BSTQ 72
#define KT   48    // 768/16 BK-iterations
__global__ __launch_bounds__(128) void qkv_gemm_tc(const float* __restrict__ x) {
    __shared__ uint32_t As[3][128 * ASTQ];   // raw fp32 bits
    __shared__ uint32_t Bs[3][16 * BSTQ];    // tf32 bits (pre-converted)

    const uint32_t* W = g_wt + blockIdx.y * (NEMBD * HS);
    uint32_t* out;
    float oscale;
    if (blockIdx.y == 0)      { out = g_q; oscale = 0.125f; }
    else if (blockIdx.y == 1) { out = g_k; oscale = 1.0f; }
    else                      { out = g_v; oscale = 1.0f; }

    const int tid  = threadIdx.x;
    const int warp = tid >> 5;
    const int lane = tid & 31;
    const int g    = lane >> 2;
    const int tig  = lane & 3;
    const int row0 = blockIdx.x * 128;

    const int ar = tid >> 2;            // A row for i=0 (rows ar, ar+32, ...)
    const int ac = (tid & 3) * 4;
    const int br = tid >> 4;
    const int bc = (tid & 15) * 4;

    float acc[2][8][4];
#pragma unroll
    for (int mt = 0; mt < 2; mt++)
#pragma unroll
        for (int nt = 0; nt < 8; nt++)
#pragma unroll
            for (int i = 0; i < 4; i++) acc[mt][nt][i] = 0.f;

#define QKV_ISSUE(s, k0)                                                          \
    do {                                                                          \
        _Pragma("unroll")                                                         \
        for (int i = 0; i < 4; i++) {                                             \
            int r = ar + i * 32;                                                  \
            cp_async16(smem_u32(&As[s][r * ASTQ + ac]),                           \
                       &x[(size_t)(row0 + r) * NEMBD + (k0) + ac]);               \
        }                                                                         \
        _Pragma("unroll")                                                         \
        for (int i = 0; i < 2; i++) {                                             \
            int r = br + i * 8;                                                   \
            cp_async16(smem_u32(&Bs[s][r * BSTQ + bc]),                           \
                       &W[(size_t)((k0) + r) * HS + bc]);                         \
        }                                                                         \
        asm volatile("cp.async.commit_group;");                                   \
    } while (0)

    QKV_ISSUE(0, 0);
    QKV_ISSUE(1, 16);

    for (int it = 0; it < KT; it++) {
        if (it == KT - 1) asm volatile("cp.async.wait_group 0;");
        else              asm volatile("cp.async.wait_group 1;");
        __syncthreads();

        if (it + 2 < KT) QKV_ISSUE((it + 2) % 3, (it + 2) * 16);

        const uint32_t* as = As[it % 3];
        const uint32_t* bs = Bs[it % 3];

#pragma unroll
        for (int kk = 0; kk < 2; kk++) {
            uint32_t af[2][4];
#pragma unroll
            for (int mt = 0; mt < 2; mt++) {
                const int m0 = warp * 32 + mt * 16;
                af[mt][0] = u2tf32(as[(m0 + g) * ASTQ + kk * 8 + tig]);
                af[mt][1] = u2tf32(as[(m0 + g + 8) * ASTQ + kk * 8 + tig]);
                af[mt][2] = u2tf32(as[(m0 + g) * ASTQ + kk * 8 + tig + 4]);
                af[mt][3] = u2tf32(as[(m0 + g + 8) * ASTQ + kk * 8 + tig + 4]);
            }
#pragma unroll
            for (int nt = 0; nt < 8; nt++) {
                uint32_t b0 = bs[(kk * 8 + tig) * BSTQ + nt * 8 + g];
                uint32_t b1 = bs[(kk * 8 + tig + 4) * BSTQ + nt * 8 + g];
                mma_tf32(acc[0][nt], af[0][0], af[0][1], af[0][2], af[0][3], b0, b1);
                mma_tf32(acc[1][nt], af[1][0], af[1][1], af[1][2], af[1][3], b0, b1);
            }
        }
    }

    // epilogue: scale (Q only) + convert to tf32 bits
#pragma unroll
    for (int mt = 0; mt < 2; mt++) {
        const int r0 = row0 + warp * 32 + mt * 16 + g;
#pragma unroll
        for (int nt = 0; nt < 8; nt++) {
            const int c = nt * 8 + 2 * tig;
            *(uint2*)&out[(size_t)r0 * HS + c] =
                make_uint2(f2tf32(acc[mt][nt][0] * oscale), f2tf32(acc[mt][nt][1] * oscale));
            *(uint2*)&out[(size_t)(r0 + 8) * HS + c] =
                make_uint2(f2tf32(acc[mt][nt][2] * oscale), f2tf32(acc[mt][nt][3] * oscale));
        }
    }
}

// ---------------- flash attention partial (tensor cores, split along keys) --
// grid = (4 chunks, 32 qblocks, 8 batches), 128 threads (4 warps)
// cp.async pipeline: K double-buffered, V single-buffered (proven R13: ~52us)
#define KSTK 68
#define KSTV 72
#define KW   (64 * KSTK)
#define ATTN_SMEM_BYTES ((2 * KW + 64 * KSTV) * 4)
__global__ __launch_bounds__(128) void attn_partial_tc() {
    extern __shared__ uint32_t dsm[];
    uint32_t* const Kb0 = dsm;
    uint32_t* const Kb1 = dsm + KW;
    uint32_t* const Vsh = dsm + 2 * KW;

    const int chunk = blockIdx.x;
    const int qb    = blockIdx.y;        // 0..31, 64 rows each
    const int b     = blockIdx.z;

    const int nkb = qb + 1;              // 64-key tiles needed (causal)
    const int kb0 = chunk * 8;
    if (kb0 >= nkb) return;
    const int kb1 = (kb0 + 8 < nkb) ? kb0 + 8 : nkb;

    const int tid  = threadIdx.x;
    const int warp = tid >> 5;
    const int lane = tid & 31;
    const int g    = lane >> 2;
    const int tig  = lane & 3;
    const int qrow0 = qb * 64;           // block's first q row (within batch)

#define ATTN_ISSUE_K(buf, kb_)                                                    \
    do {                                                                          \
        _Pragma("unroll")                                                         \
        for (int i = 0; i < 8; i++) {                                             \
            int idx = tid + i * 128;                                              \
            int r   = idx >> 4;                                                   \
            int c4  = (idx & 15) * 4;                                             \
            cp_async16(smem_u32(&(buf)[r * KSTK + c4]),                           \
                       &g_k[((size_t)(b * TOK + (kb_) * 64 + r)) * HS + c4]);     \
        }                                                                         \
        asm volatile("cp.async.commit_group;");                                   \
    } while (0)

#define ATTN_ISSUE_V(kb_)                                                         \
    do {                                                                          \
        _Pragma("unroll")                                                         \
        for (int i = 0; i < 8; i++) {                                             \
            int idx = tid + i * 128;                                              \
            int r   = idx >> 4;                                                   \
            int c4  = (idx & 15) * 4;                                             \
            cp_async16(smem_u32(&Vsh[r * KSTV + c4]),                             \
                       &g_v[((size_t)(b * TOK + (kb_) * 64 + r)) * HS + c4]);     \
        }                                                                         \
        asm volatile("cp.async.commit_group;");                                   \
    } while (0)

    // prologue: first K tile in flight while we stage Q
    ATTN_ISSUE_K(Kb0, kb0);

    // ---- stage Q (already tf32+scaled) through Vsh, pull fragments ---------
#pragma unroll
    for (int i = 0; i < 8; i++) {
        int idx = tid + i * 128;
        int r   = idx >> 4;
        int c4  = (idx & 15) * 4;
        *(uint4*)&Vsh[r * KSTV + c4] =
            *(const uint4*)&g_q[((size_t)(b * TOK + qrow0 + r)) * HS + c4];
    }
    __syncthreads();

    uint32_t qf[8][4];
    const int mrow = warp * 16;          // warp's first local row
#pragma unroll
    for (int ks = 0; ks < 8; ks++) {
        qf[ks][0] = Vsh[(mrow + g) * KSTV + ks * 8 + tig];
        qf[ks][1] = Vsh[(mrow + g + 8) * KSTV + ks * 8 + tig];
        qf[ks][2] = Vsh[(mrow + g) * KSTV + ks * 8 + tig + 4];
        qf[ks][3] = Vsh[(mrow + g + 8) * KSTV + ks * 8 + tig + 4];
    }
    __syncthreads();

    float oacc[8][4];
#pragma unroll
    for (int nt = 0; nt < 8; nt++)
#pragma unroll
        for (int i = 0; i < 4; i++) oacc[nt][i] = 0.f;

    float m0r = -INFINITY, m1r = -INFINITY;   // rows g and g+8
    float l0 = 0.f, l1 = 0.f;

    const int rg0 = qrow0 + mrow + g;         // global (in-batch) q rows
    const int rg1 = rg0 + 8;

    // shuffle sources for C-frag -> A-frag redistribution
    const int src0 = (lane & ~3) | (tig >> 1);
    const int src1 = src0 + 2;
    const bool odd = (tig & 1);

    int it = 0;
    for (int kb = kb0; kb < kb1; kb++, it++) {
        const uint32_t* Kc = (it & 1) ? Kb1 : Kb0;
        const bool hn = (kb + 1 < kb1);

        // drain K for this tile (issued one tile ago -> latency hidden)
        asm volatile("cp.async.wait_group 0;");
        __syncthreads();   // K visible to all; also: all warps done prev PV (Vsh reusable)

        ATTN_ISSUE_V(kb);                                   // group: V_i
        if (hn) {
            if (it & 1) ATTN_ISSUE_K(Kb0, kb + 1);          // group: K_{i+1}
            else        ATTN_ISSUE_K(Kb1, kb + 1);
        }

        // ---- S = Q K^T (16 x 64 per warp) ---------------------------------
        float sacc[8][4];
#pragma unroll
        for (int nt = 0; nt < 8; nt++) {
#pragma unroll
            for (int i = 0; i < 4; i++) sacc[nt][i] = 0.f;
#pragma unroll
            for (int ks = 0; ks < 8; ks++) {
                uint32_t b0 = Kc[(nt * 8 + g) * KSTK + ks * 8 + tig];
                uint32_t b1 = Kc[(nt * 8 + g) * KSTK + ks * 8 + tig + 4];
                mma_tf32(sacc[nt], qf[ks][0], qf[ks][1], qf[ks][2], qf[ks][3], b0, b1);
            }
        }

        // ---- causal mask (only the diagonal tile can clip) ----------------
        if (kb == qb) {
            const int colbase = kb * 64;
#pragma unroll
            for (int nt = 0; nt < 8; nt++) {
                const int c0 = colbase + nt * 8 + 2 * tig;
                if (c0 > rg0)     sacc[nt][0] = -INFINITY;
                if (c0 + 1 > rg0) sacc[nt][1] = -INFINITY;
                if (c0 > rg1)     sacc[nt][2] = -INFINITY;
                if (c0 + 1 > rg1) sacc[nt][3] = -INFINITY;
            }
        }

        // ---- online softmax -----------------------------------------------
        float mx0 = -INFINITY, mx1 = -INFINITY;
#pragma unroll
        for (int nt = 0; nt < 8; nt++) {
            mx0 = fmaxf(mx0, fmaxf(sacc[nt][0], sacc[nt][1]));
            mx1 = fmaxf(mx1, fmaxf(sacc[nt][2], sacc[nt][3]));
        }
        mx0 = fmaxf(mx0, __shfl_xor_sync(0xffffffffu, mx0, 1));
        mx0 = fmaxf(mx0, __shfl_xor_sync(0xffffffffu, mx0, 2));
        mx1 = fmaxf(mx1, __shfl_xor_sync(0xffffffffu, mx1, 1));
        mx1 = fmaxf(mx1, __shfl_xor_sync(0xffffffffu, mx1, 2));

        const float mn0 = fmaxf(m0r, mx0);
        const float mn1 = fmaxf(m1r, mx1);
        const float alpha0 = __expf(m0r - mn0);   // first iter: exp(-inf)=0
        const float alpha1 = __expf(m1r - mn1);
        m0r = mn0; m1r = mn1;

        float ps0 = 0.f, ps1 = 0.f;
#pragma unroll
        for (int nt = 0; nt < 8; nt++) {
            sacc[nt][0] = __expf(sacc[nt][0] - mn0);
            sacc[nt][1] = __expf(sacc[nt][1] - mn0);
            sacc[nt][2] = __expf(sacc[nt][2] - mn1);
            sacc[nt][3] = __expf(sacc[nt][3] - mn1);
            ps0 += sacc[nt][0] + sacc[nt][1];
            ps1 += sacc[nt][2] + sacc[nt][3];
        }
        ps0 += __shfl_xor_sync(0xffffffffu, ps0, 1);
        ps0 += __shfl_xor_sync(0xffffffffu, ps0, 2);
        ps1 += __shfl_xor_sync(0xffffffffu, ps1, 1);
        ps1 += __shfl_xor_sync(0xffffffffu, ps1, 2);
        l0 = l0 * alpha0 + ps0;
        l1 = l1 * alpha1 + ps1;

#pragma unroll
        for (int nt = 0; nt < 8; nt++) {
            oacc[nt][0] *= alpha0; oacc[nt][1] *= alpha0;
            oacc[nt][2] *= alpha1; oacc[nt][3] *= alpha1;
        }

        // drain V (issued at tile top -> hidden behind S+softmax)
        if (hn) asm volatile("cp.async.wait_group 1;");
        else    asm volatile("cp.async.wait_group 0;");
        __syncthreads();

        // ---- O += P V : P redistributed C-frag -> A-frag via shuffles ------
#pragma unroll
        for (int ks = 0; ks < 8; ks++) {
            const float p0a = __shfl_sync(0xffffffffu, sacc[ks][0], src0);
            const float p1a = __shfl_sync(0xffffffffu, sacc[ks][1], src0);
            const float p2a = __shfl_sync(0xffffffffu, sacc[ks][2], src0);
            const float p3a = __shfl_sync(0xffffffffu, sacc[ks][3], src0);
            const float p0b = __shfl_sync(0xffffffffu, sacc[ks][0], src1);
            const float p1b = __shfl_sync(0xffffffffu, sacc[ks][1], src1);
            const float p2b = __shfl_sync(0xffffffffu, sacc[ks][2], src1);
            const float p3b = __shfl_sync(0xffffffffu, sacc[ks][3], src1);
            const uint32_t pa0 = f2tf32(odd ? p1a : p0a);
            const uint32_t pa1 = f2tf32(odd ? p3a : p2a);
            const uint32_t pa2 = f2tf32(odd ? p1b : p0b);
            const uint32_t pa3 = f2tf32(odd ? p3b : p2b);
#pragma unroll
            for (int nt = 0; nt < 8; nt++) {
                uint32_t b0 = Vsh[(ks * 8 + tig) * KSTV + nt * 8 + g];
                uint32_t b1 = Vsh[(ks * 8 + tig + 4) * KSTV + nt * 8 + g];
                mma_tf32(oacc[nt], pa0, pa1, pa2, pa3, b0, b1);
            }
        }
        // no trailing sync: next iteration's top sync protects Vsh/K buffers
    }

    // ---- write partials ----------------------------------------------------
    const int unit = (b * 32 + qb) * 4 + chunk;
    const int lr0 = mrow + g;            // local rows within 64
    const int lr1 = lr0 + 8;
    if (tig == 0) {
        g_part_m[unit * 64 + lr0] = m0r;
        g_part_m[unit * 64 + lr1] = m1r;
        g_part_l[unit * 64 + lr0] = l0;
        g_part_l[unit * 64 + lr1] = l1;
    }
#pragma unroll
    for (int nt = 0; nt < 8; nt++) {
        const int c = nt * 8 + 2 * tig;
        *(float2*)&g_part_o[((size_t)(unit * 64 + lr0)) * HS + c] =
            make_float2(oacc[nt][0], oacc[nt][1]);
        *(float2*)&g_part_o[((size_t)(unit * 64 + lr1)) * HS + c] =
            make_float2(oacc[nt][2], oacc[nt][3]);
    }
}

// ---------------- combine split-K partials (8 threads per row) --------------
__global__ __launch_bounds__(256) void attn_combine(float* __restrict__ out) {
    const int gid = blockIdx.x * 256 + threadIdx.x;   // 0..131071
    const int row = gid >> 3;                         // 0..16383 (b*2048+t)
    const int part = gid & 7;                         // 8-float slice of HS
    const int b = row >> 11;
    const int t = row & 2047;
    const int qb = t >> 6;
    const int lane = t & 63;
    const int nchunk = (qb + 1 + 7) / 8;              // 1..4 active chunks
    const int base_unit = (b * 32 + qb) * 4;

    float M = -INFINITY;
#pragma unroll 4
    for (int c = 0; c < nchunk; c++)
        M = fmaxf(M, g_part_m[(base_unit + c) * 64 + lane]);

    float w[4];
    float L = 0.f;
#pragma unroll 4
    for (int c = 0; c < nchunk; c++) {
        float wm = __expf(g_part_m[(base_unit + c) * 64 + lane] - M);
        w[c] = wm;
        L += wm * g_part_l[(base_unit + c) * 64 + lane];
    }
    const float inv = 1.f / L;

    float* op = out + (size_t)row * HS + part * 8;
#pragma unroll
    for (int i = 0; i < 2; i++) {
        float4 acc = make_float4(0.f, 0.f, 0.f, 0.f);
#pragma unroll 4
        for (int c = 0; c < nchunk; c++) {
            const float* po = g_part_o + ((size_t)((base_unit + c) * 64 + lane)) * HS
                            + part * 8;
            float4 v = *(const float4*)&po[i * 4];
            acc.x += w[c] * v.x; acc.y += w[c] * v.y;
            acc.z += w[c] * v.z; acc.w += w[c] * v.w;
        }
        acc.x *= inv; acc.y *= inv; acc.z *= inv; acc.w *= inv;
        *(float4*)&op[i * 4] = acc;
    }
}

// ---------------- launch ----------------------------------------------------
extern "C" void kernel_launch(void* const* d_in, const int* in_sizes, int n_in,
                              void* d_out, int out_size) {
    const float* x  = (const float*)d_in[0];
    const float* Wk = (const float*)d_in[1];
    const float* Wq = (const float*)d_in[2];
    const float* Wv = (const float*)d_in[3];
    float* out = (float*)d_out;

    cudaFuncSetAttribute(attn_partial_tc,
                         cudaFuncAttributeMaxDynamicSharedMemorySize,
                         ATTN_SMEM_BYTES);

    w_convert<<<dim3(3 * NEMBD * HS / 4 / 256), 256>>>(Wq, Wk, Wv);
    qkv_gemm_tc<<<dim3(MROWS / 128, 3), 128>>>(x);
    attn_partial_tc<<<dim3(4, 32, BATCH), 128, ATTN_SMEM_BYTES>>>();
    attn_combine<<<dim3(MROWS * 8 / 256), 256>>>(out);
}